// round 12
// baseline (speedup 1.0000x reference)
#include <cuda_runtime.h>
#include <math.h>
#include <stdint.h>

// Problem constants
#define BB 2
#define TT 2048
#define CC 1024
#define HH 16
#define HS 64
#define NROWS (BB*TT)        // 4096
#define LN_EPS 1e-5f

// ---------------------------------------------------------------------------
// Scratch
// ---------------------------------------------------------------------------
__device__ float g_h   [NROWS*CC];
__device__ float g_wqkv[CC*3*CC];      // packed [C, 3C] qkv weight (tf32)
__device__ float g_bqkv[3*CC];
__device__ float g_qkv [NROWS*3*CC];
__device__ float g_attn[NROWS*CC];
__device__ float g_x1  [NROWS*CC];
__device__ float g_h2  [NROWS*CC];
__device__ float g_ff  [NROWS*4*CC];
__device__ float g_wor [CC*CC];        // tf32-rounded Wo
__device__ float g_w1r [CC*4*CC];      // tf32-rounded W1
__device__ float g_w2r [4*CC*CC];      // tf32-rounded W2

__device__ __forceinline__ float to_tf32(float x) {
    uint32_t u;
    asm("cvt.rna.tf32.f32 %0, %1;" : "=r"(u) : "f"(x));
    return __uint_as_float(u);
}
__device__ __forceinline__ float ex2_mufu(float y) {
    float r;
    asm("ex2.approx.ftz.f32 %0, %1;" : "=f"(r) : "f"(y));
    return r;
}
__device__ __forceinline__ float ex2_poly(float y) {
    float r = y + 12582912.f;
    int   n = __float_as_int(r);
    float t = r - 12582912.f;
    float f = y - t;
    float p = 0.00961813f;
    p = fmaf(p, f, 0.05550411f);
    p = fmaf(p, f, 0.24022651f);
    p = fmaf(p, f, 0.69314718f);
    p = fmaf(p, f, 1.0f);
    return __int_as_float(__float_as_int(p) + (n << 23));
}
__device__ __forceinline__ uint32_t pack_bf16x2(float lo, float hi) {
    uint32_t r;
    asm("cvt.rn.bf16x2.f32 %0, %1, %2;" : "=r"(r) : "f"(hi), "f"(lo));
    return r;
}
__device__ __forceinline__ void cp16(uint32_t dst, const void* src) {
    asm volatile("cp.async.cg.shared.global [%0], [%1], 16;\n"
                 :: "r"(dst), "l"(src));
}
#define CP_COMMIT() asm volatile("cp.async.commit_group;\n" ::: "memory")
#define CP_WAIT(n)  asm volatile("cp.async.wait_group %0;\n" :: "n"(n) : "memory")

// ---------------------------------------------------------------------------
// Pack Wq/Wk/Wv -> g_wqkv [C, 3C]  (tf32-rounded)  [R6 verified]
// ---------------------------------------------------------------------------
__global__ void pack_qkv_kernel(const float* __restrict__ Wq,
                                const float* __restrict__ Wk,
                                const float* __restrict__ Wv,
                                const float* __restrict__ bq,
                                const float* __restrict__ bk,
                                const float* __restrict__ bv) {
    int e = blockIdx.x * blockDim.x + threadIdx.x;
    if (e < HH*CC*HS) {
        int d = e % HS;
        int c = (e / HS) % CC;
        int h = e / (HS*CC);
        int col = h*HS + d;
        g_wqkv[(size_t)c*3*CC +        col] = to_tf32(Wq[e]);
        g_wqkv[(size_t)c*3*CC + CC   + col] = to_tf32(Wk[e]);
        g_wqkv[(size_t)c*3*CC + 2*CC + col] = to_tf32(Wv[e]);
    }
    if (e < CC) {
        g_bqkv[e]        = bq[e];
        g_bqkv[CC + e]   = bk[e];
        g_bqkv[2*CC + e] = bv[e];
    }
}

// ---------------------------------------------------------------------------
// Round Wo / W1 / W2 to tf32 (one-time copy)  [R6 verified]
// ---------------------------------------------------------------------------
__global__ void round_w_kernel(const float* __restrict__ Wo,
                               const float* __restrict__ W1,
                               const float* __restrict__ W2) {
    int i4 = blockIdx.x * blockDim.x + threadIdx.x;
    const int NWO = CC*CC/4, NW1 = CC*4*CC/4, NW2 = 4*CC*CC/4;
    if (i4 < NWO) {
        float4 v = *(const float4*)&Wo[i4*4];
        v.x = to_tf32(v.x); v.y = to_tf32(v.y);
        v.z = to_tf32(v.z); v.w = to_tf32(v.w);
        *(float4*)&g_wor[i4*4] = v;
    } else if (i4 < NWO + NW1) {
        int j = i4 - NWO;
        float4 v = *(const float4*)&W1[(size_t)j*4];
        v.x = to_tf32(v.x); v.y = to_tf32(v.y);
        v.z = to_tf32(v.z); v.w = to_tf32(v.w);
        *(float4*)&g_w1r[(size_t)j*4] = v;
    } else if (i4 < NWO + NW1 + NW2) {
        int j = i4 - NWO - NW1;
        float4 v = *(const float4*)&W2[(size_t)j*4];
        v.x = to_tf32(v.x); v.y = to_tf32(v.y);
        v.z = to_tf32(v.z); v.w = to_tf32(v.w);
        *(float4*)&g_w2r[(size_t)j*4] = v;
    }
}

// ---------------------------------------------------------------------------
// LayerNorm over sequence axis; block (16 cols, 64 t-lanes), grid 128 CTAs
// ---------------------------------------------------------------------------
__global__ void __launch_bounds__(1024)
ln_seq_kernel(const float* __restrict__ x,
              const float* __restrict__ gamma,
              const float* __restrict__ beta,
              float* __restrict__ out) {
    int b  = blockIdx.y;
    int tx = threadIdx.x, ty = threadIdx.y;   // tx 0..15, ty 0..63
    int c  = blockIdx.x * 16 + tx;
    const float* xp = x   + (size_t)b*TT*CC + c;
    float*       op = out + (size_t)b*TT*CC + c;

    float s = 0.f, sq = 0.f;
    for (int t = ty; t < TT; t += 64) {
        float v = xp[(size_t)t*CC];
        s += v; sq += v*v;
    }
    __shared__ float ssum[64][17];
    __shared__ float ssq [64][17];
    ssum[ty][tx] = s; ssq[ty][tx] = sq;
    __syncthreads();
    for (int off = 32; off > 0; off >>= 1) {
        if (ty < off) {
            ssum[ty][tx] += ssum[ty+off][tx];
            ssq [ty][tx] += ssq [ty+off][tx];
        }
        __syncthreads();
    }
    __shared__ float meanv[16], rstdv[16];
    if (ty == 0) {
        float mean = ssum[0][tx] * (1.0f / TT);
        float var  = (ssq[0][tx] - (float)TT * mean * mean) * (1.0f / (TT - 1));
        meanv[tx]  = mean;
        rstdv[tx]  = 1.0f / (sqrtf(var) + LN_EPS);
    }
    __syncthreads();
    float mean = meanv[tx], rstd = rstdv[tx];
    float g = gamma[c], bt = beta[c];
    for (int t = ty; t < TT; t += 64) {
        float v = xp[(size_t)t*CC];
        op[(size_t)t*CC] = to_tf32(g * ((v - mean) * rstd) + bt);
    }
}

// ---------------------------------------------------------------------------
// TF32 GEMM, 128x128 tile, 8 warps (4m x 2n), warp 32x64.  [R6 layout]
// 3-stage cp.async pipeline, ONE __syncthreads per k-iter.  2 CTAs/SM.
// ---------------------------------------------------------------------------
#define MMA_TF32(d, a, b)                                                     \
    asm volatile(                                                             \
        "mma.sync.aligned.m16n8k8.row.col.f32.tf32.tf32.f32 "                 \
        "{%0,%1,%2,%3},{%4,%5,%6,%7},{%8,%9},{%0,%1,%2,%3};\n"                \
        : "+f"((d)[0]), "+f"((d)[1]), "+f"((d)[2]), "+f"((d)[3])              \
        : "r"((a)[0]), "r"((a)[1]), "r"((a)[2]), "r"((a)[3]),                 \
          "r"((b)[0]), "r"((b)[1]))

#define AS_FLOATS 4608    /* 128*36 per stage */
#define BS_FLOATS 4352    /* 32*136 per stage */
#define NSTAGE 3
#define GEMM_SMEM (NSTAGE*(AS_FLOATS + BS_FLOATS)*4)   /* 107520 B */

template<int DOBIAS, int DORELU, int DORES, int DOROUND>
__global__ void __launch_bounds__(256, 2)
gemm_tc_kernel(const float* __restrict__ A, const float* __restrict__ Bm,
               const float* __restrict__ bias, const float* __restrict__ res,
               float* __restrict__ Cm, int M, int N, int K) {
    extern __shared__ float smg[];
    int tid  = threadIdx.x;
    int lane = tid & 31, wid = tid >> 5;
    int wm = (wid >> 1) * 32;
    int wn = (wid & 1) * 64;
    int g  = lane >> 2;
    int tg = lane & 3;
    int m0 = blockIdx.y * 128, n0 = blockIdx.x * 128;

    float acc[2][8][4];
#pragma unroll
    for (int mf = 0; mf < 2; mf++)
#pragma unroll
        for (int nf = 0; nf < 8; nf++)
#pragma unroll
            for (int r = 0; r < 4; r++) acc[mf][nf][r] = 0.f;

    uint32_t smg_u = (uint32_t)__cvta_generic_to_shared(smg);
    int nk = K >> 5;

    int ar = tid >> 3, ac = (tid & 7) * 4;
    int br = tid >> 5, bc = (tid & 31) * 4;

    // stage issue helper (inlined twice)
#define ISSUE_STAGE(stg, k0)                                                  \
    do {                                                                      \
        uint32_t as_b = smg_u + ((stg)*AS_FLOATS)*4;                          \
        uint32_t bs_b = smg_u + (NSTAGE*AS_FLOATS + (stg)*BS_FLOATS)*4;       \
        _Pragma("unroll")                                                     \
        for (int p = 0; p < 4; p++)                                           \
            cp16(as_b + ((ar + 32*p)*36 + ac)*4,                              \
                 &A[(size_t)(m0 + ar + 32*p)*K + (k0) + ac]);                 \
        _Pragma("unroll")                                                     \
        for (int p = 0; p < 4; p++)                                           \
            cp16(bs_b + ((br + 8*p)*136 + bc)*4,                              \
                 &Bm[(size_t)((k0) + br + 8*p)*N + n0 + bc]);                 \
        CP_COMMIT();                                                          \
    } while (0)

    // prologue: stages 0 and 1
    ISSUE_STAGE(0, 0);
    if (nk > 1) ISSUE_STAGE(1, 32);

    for (int i = 0; i < nk; i++) {
        if (i == nk - 1) { CP_WAIT(0); } else { CP_WAIT(1); }
        __syncthreads();

        // issue stage i+2 (writes buf (i+2)%3 == buf (i-1)%3, whose readers
        // finished before the barrier above)
        if (i + 2 < nk) {
            int stg = (i + 2) % NSTAGE;
            int k0 = (i + 2) << 5;
            ISSUE_STAGE(stg, k0);
        }

        int buf = i % NSTAGE;
        const float* As = smg + buf*AS_FLOATS;
        const float* Bs = smg + NSTAGE*AS_FLOATS + buf*BS_FLOATS;

#pragma unroll
        for (int ks = 0; ks < 4; ks++) {
            int kk = ks * 8;
            uint32_t afr[2][4];
#pragma unroll
            for (int mf = 0; mf < 2; mf++) {
                int r = wm + mf*16 + g;
                afr[mf][0] = __float_as_uint(As[(r    )*36 + kk + tg    ]);
                afr[mf][1] = __float_as_uint(As[(r + 8)*36 + kk + tg    ]);
                afr[mf][2] = __float_as_uint(As[(r    )*36 + kk + tg + 4]);
                afr[mf][3] = __float_as_uint(As[(r + 8)*36 + kk + tg + 4]);
            }
#pragma unroll
            for (int nf = 0; nf < 8; nf++) {
                uint32_t bfr[2];
                bfr[0] = __float_as_uint(Bs[(kk + tg    )*136 + wn + nf*8 + g]);
                bfr[1] = __float_as_uint(Bs[(kk + tg + 4)*136 + wn + nf*8 + g]);
#pragma unroll
                for (int mf = 0; mf < 2; mf++)
                    MMA_TF32(acc[mf][nf], afr[mf], bfr);
            }
        }
    }
#undef ISSUE_STAGE

#pragma unroll
    for (int mf = 0; mf < 2; mf++) {
#pragma unroll
        for (int nf = 0; nf < 8; nf++) {
            int r  = m0 + wm + mf*16 + g;
            int cb = n0 + wn + nf*8 + 2*tg;
            float2 v0 = make_float2(acc[mf][nf][0], acc[mf][nf][1]);
            float2 v1 = make_float2(acc[mf][nf][2], acc[mf][nf][3]);
            if (DOBIAS) {
                float2 bsv = *(const float2*)&bias[cb];
                v0.x += bsv.x; v0.y += bsv.y;
                v1.x += bsv.x; v1.y += bsv.y;
            }
            if (DORELU) {
                v0.x = fmaxf(v0.x, 0.f); v0.y = fmaxf(v0.y, 0.f);
                v1.x = fmaxf(v1.x, 0.f); v1.y = fmaxf(v1.y, 0.f);
            }
            if (DORES) {
                float2 r0 = *(const float2*)&res[(size_t)r*N + cb];
                float2 r1 = *(const float2*)&res[(size_t)(r+8)*N + cb];
                v0.x += r0.x; v0.y += r0.y;
                v1.x += r1.x; v1.y += r1.y;
            }
            if (DOROUND) {
                v0.x = to_tf32(v0.x); v0.y = to_tf32(v0.y);
                v1.x = to_tf32(v1.x); v1.y = to_tf32(v1.y);
            }
            *(float2*)&Cm[(size_t)r*N + cb]     = v0;
            *(float2*)&Cm[(size_t)(r+8)*N + cb] = v1;
        }
    }
}

// ---------------------------------------------------------------------------
// bf16 tensor-core flash attention (verified R6)
// ---------------------------------------------------------------------------
#define QS32 36
#define KS32 36
#define VS32 36
#define SM32_QS 0
#define SM32_KS (128*QS32)
#define SM32_VT (SM32_KS + 64*KS32)
#define ATTN_SMEM ((SM32_VT + 64*VS32)*4)
#define QSCALE 0.18033688f

#define MMA_BF16(d, a, b)                                                     \
    asm volatile(                                                             \
        "mma.sync.aligned.m16n8k16.row.col.f32.bf16.bf16.f32 "                \
        "{%0,%1,%2,%3},{%4,%5,%6,%7},{%8,%9},{%0,%1,%2,%3};\n"                \
        : "+f"((d)[0]), "+f"((d)[1]), "+f"((d)[2]), "+f"((d)[3])              \
        : "r"((a)[0]), "r"((a)[1]), "r"((a)[2]), "r"((a)[3]),                 \
          "r"((b)[0]), "r"((b)[1]))

__global__ void __launch_bounds__(256, 2) attn_tc_kernel() {
    extern __shared__ uint32_t smu[];
    uint32_t* Qs = smu + SM32_QS;
    uint32_t* Ks = smu + SM32_KS;
    uint32_t* Vt = smu + SM32_VT;

    int tid = threadIdx.x, lane = tid & 31, wid = tid >> 5;
    int g = lane >> 2, tg = lane & 3;
    int b = blockIdx.z, h = blockIdx.y;
    int tq0 = blockIdx.x * 128;
    int wr = wid * 16;

    const float* qbase = g_qkv + (size_t)b*TT*3*CC + (size_t)h*HS;
    const float* kbase = qbase + CC;
    const float* vbase = qbase + 2*CC;

#pragma unroll
    for (int p = 0; p < 8; p++) {
        int idx = tid + p*256;
        int r = idx >> 4, c4 = idx & 15;
        float4 v = *(const float4*)&qbase[(size_t)(tq0 + r)*3*CC + c4*4];
        Qs[r*QS32 + c4*2    ] = pack_bf16x2(v.x*QSCALE, v.y*QSCALE);
        Qs[r*QS32 + c4*2 + 1] = pack_bf16x2(v.z*QSCALE, v.w*QSCALE);
    }

    float o[8][4];
#pragma unroll
    for (int i = 0; i < 8; i++)
#pragma unroll
        for (int j = 0; j < 4; j++) o[i][j] = 0.f;
    float lsum0 = 0.f, lsum1 = 0.f;

    __syncthreads();

    for (int kt = 0; kt < TT; kt += 64) {
#pragma unroll
        for (int p = 0; p < 4; p++) {
            int idx = tid + p*256;
            int r = idx >> 4, c4 = idx & 15;
            float4 v = *(const float4*)&kbase[(size_t)(kt + r)*3*CC + c4*4];
            Ks[r*KS32 + c4*2    ] = pack_bf16x2(v.x, v.y);
            Ks[r*KS32 + c4*2 + 1] = pack_bf16x2(v.z, v.w);
        }
#pragma unroll
        for (int p = 0; p < 2; p++) {
            int idx = tid + p*256;
            int sp = idx & 31, dg = idx >> 5;
            int d0 = dg * 4;
            float4 v0 = *(const float4*)&vbase[(size_t)(kt + 2*sp    )*3*CC + d0];
            float4 v1 = *(const float4*)&vbase[(size_t)(kt + 2*sp + 1)*3*CC + d0];
            Vt[(d0    )*VS32 + sp] = pack_bf16x2(v0.x, v1.x);
            Vt[(d0 + 1)*VS32 + sp] = pack_bf16x2(v0.y, v1.y);
            Vt[(d0 + 2)*VS32 + sp] = pack_bf16x2(v0.z, v1.z);
            Vt[(d0 + 3)*VS32 + sp] = pack_bf16x2(v0.w, v1.w);
        }
        __syncthreads();

        float s[8][4];
#pragma unroll
        for (int nf = 0; nf < 8; nf++)
#pragma unroll
            for (int j = 0; j < 4; j++) s[nf][j] = 0.f;

#pragma unroll
        for (int c = 0; c < 4; c++) {
            int c8 = c * 8;
            uint32_t aq[4];
            aq[0] = Qs[(wr+g  )*QS32 + c8 + tg    ];
            aq[1] = Qs[(wr+g+8)*QS32 + c8 + tg    ];
            aq[2] = Qs[(wr+g  )*QS32 + c8 + tg + 4];
            aq[3] = Qs[(wr+g+8)*QS32 + c8 + tg + 4];
#pragma unroll
            for (int nf = 0; nf < 8; nf++) {
                uint32_t bk[2];
                bk[0] = Ks[(nf*8+g)*KS32 + c8 + tg    ];
                bk[1] = Ks[(nf*8+g)*KS32 + c8 + tg + 4];
                MMA_BF16(s[nf], aq, bk);
            }
        }

#pragma unroll
        for (int nf = 0; nf < 8; nf++) {
            if (nf < 4) {
                s[nf][0] = ex2_mufu(fminf(s[nf][0], 80.f));
                s[nf][1] = ex2_mufu(fminf(s[nf][1], 80.f));
                s[nf][2] = ex2_mufu(fminf(s[nf][2], 80.f));
                s[nf][3] = ex2_mufu(fminf(s[nf][3], 80.f));
            } else {
                s[nf][0] = ex2_poly(fminf(fmaxf(s[nf][0], -80.f), 80.f));
                s[nf][1] = ex2_poly(fminf(fmaxf(s[nf][1], -80.f), 80.f));
                s[nf][2] = ex2_poly(fminf(fmaxf(s[nf][2], -80.f), 80.f));
                s[nf][3] = ex2_poly(fminf(fmaxf(s[nf][3], -80.f), 80.f));
            }
            lsum0 += s[nf][0] + s[nf][1];
            lsum1 += s[nf][2] + s[nf][3];
        }

#pragma unroll
        for (int j = 0; j < 4; j++) {
            uint32_t ap[4];
            ap[0] = pack_bf16x2(s[2*j  ][0], s[2*j  ][1]);
            ap[1] = pack_bf16x2(s[2*j  ][2], s[2*j  ][3]);
            ap[2] = pack_bf16x2(s[2*j+1][0], s[2*j+1][1]);
            ap[3] = pack_bf16x2(s[2*j+1][2], s[2*j+1][3]);
            int c8 = j * 8;
#pragma unroll
            for (int nf = 0; nf < 8; nf++) {
                uint32_t bv[2];
                bv[0] = Vt[(nf*8+g)*VS32 + c8 + tg    ];
                bv[1] = Vt[(nf*8+g)*VS32 + c8 + tg + 4];
                MMA_BF16(o[nf], ap, bv);
            }
        }
        __syncthreads();
    }

    lsum0 += __shfl_xor_sync(0xffffffffu, lsum0, 1);
    lsum0 += __shfl_xor_sync(0xffffffffu, lsum0, 2);
    lsum1 += __shfl_xor_sync(0xffffffffu, lsum1, 1);
    lsum1 += __shfl_xor_sync(0xffffffffu, lsum1, 2);
    float inv0 = 1.0f / lsum0, inv1 = 1.0f / lsum1;

    int row0 = b*TT + tq0 + wr + g;
#pragma unroll
    for (int nf = 0; nf < 8; nf++) {
        int col = h*HS + nf*8 + 2*tg;
        float2 v0 = make_float2(to_tf32(o[nf][0]*inv0), to_tf32(o[nf][1]*inv0));
        float2 v1 = make_float2(to_tf32(o[nf][2]*inv1), to_tf32(o[nf][3]*inv1));
        *(float2*)&g_attn[(size_t)row0*CC + col]     = v0;
        *(float2*)&g_attn[(size_t)(row0+8)*CC + col] = v1;
    }
}

// ---------------------------------------------------------------------------
// Launch
// ---------------------------------------------------------------------------
extern "C" void kernel_launch(void* const* d_in, const int* in_sizes, int n_in,
                              void* d_out, int out_size) {
    const float* x      = (const float*)d_in[0];
    const float* Wq     = (const float*)d_in[1];
    const float* bq     = (const float*)d_in[2];
    const float* Wk     = (const float*)d_in[3];
    const float* bk     = (const float*)d_in[4];
    const float* Wv     = (const float*)d_in[5];
    const float* bv     = (const float*)d_in[6];
    const float* Wo     = (const float*)d_in[7];
    const float* bo     = (const float*)d_in[8];
    const float* W1     = (const float*)d_in[9];
    const float* b1     = (const float*)d_in[10];
    const float* W2     = (const float*)d_in[11];
    const float* b2     = (const float*)d_in[12];
    const float* gamma1 = (const float*)d_in[13];
    const float* beta1  = (const float*)d_in[14];
    const float* gamma2 = (const float*)d_in[15];
    const float* beta2  = (const float*)d_in[16];
    float* out = (float*)d_out;

    float *p_h, *p_wqkv, *p_bqkv, *p_qkv, *p_attn, *p_x1, *p_h2, *p_ff;
    float *p_wor, *p_w1r, *p_w2r;
    cudaGetSymbolAddress((void**)&p_h,    g_h);
    cudaGetSymbolAddress((void**)&p_wqkv, g_wqkv);
    cudaGetSymbolAddress((void**)&p_bqkv, g_bqkv);
    cudaGetSymbolAddress((void**)&p_qkv,  g_qkv);
    cudaGetSymbolAddress((void**)&p_attn, g_attn);
    cudaGetSymbolAddress((void**)&p_x1,   g_x1);
    cudaGetSymbolAddress((void**)&p_h2,   g_h2);
    cudaGetSymbolAddress((void**)&p_ff,   g_ff);
    cudaGetSymbolAddress((void**)&p_wor,  g_wor);
    cudaGetSymbolAddress((void**)&p_w1r,  g_w1r);
    cudaGetSymbolAddress((void**)&p_w2r,  g_w2r);

    cudaFuncSetAttribute(attn_tc_kernel,
                         cudaFuncAttributeMaxDynamicSharedMemorySize, ATTN_SMEM);
    cudaFuncSetAttribute(gemm_tc_kernel<1,0,0,0>,
                         cudaFuncAttributeMaxDynamicSharedMemorySize, GEMM_SMEM);
    cudaFuncSetAttribute(gemm_tc_kernel<1,0,1,0>,
                         cudaFuncAttributeMaxDynamicSharedMemorySize, GEMM_SMEM);
    cudaFuncSetAttribute(gemm_tc_kernel<1,1,0,1>,
                         cudaFuncAttributeMaxDynamicSharedMemorySize, GEMM_SMEM);

    // 0. weight prep (tf32-rounded copies)
    pack_qkv_kernel<<<(HH*CC*HS + 255)/256, 256>>>(Wq, Wk, Wv, bq, bk, bv);
    round_w_kernel<<<(9*CC*CC/4 + 255)/256, 256>>>(Wo, W1, W2);

    // 1. LN1
    ln_seq_kernel<<<dim3(CC/16, BB), dim3(16, 64)>>>(x, gamma1, beta1, p_h);

    // 2. QKV GEMM: [4096,1024] @ [1024,3072]
    gemm_tc_kernel<1,0,0,0><<<dim3(3*CC/128, NROWS/128), 256, GEMM_SMEM>>>(
        p_h, p_wqkv, p_bqkv, nullptr, p_qkv, NROWS, 3*CC, CC);

    // 3. attention
    attn_tc_kernel<<<dim3(TT/128, HH, BB), 256, ATTN_SMEM>>>();

    // 4. output projection + residual
    gemm_tc_kernel<1,0,1,0><<<dim3(CC/128, NROWS/128), 256, GEMM_SMEM>>>(
        p_attn, p_wor, bo, x, p_x1, NROWS, CC, CC);

    // 5. LN2
    ln_seq_kernel<<<dim3(CC/16, BB), dim3(16, 64)>>>(p_x1, gamma2, beta2, p_h2);

    // 6. FF1 + relu (rounded output)
    gemm_tc_kernel<1,1,0,1><<<dim3(4*CC/128, NROWS/128), 256, GEMM_SMEM>>>(
        p_h2, p_w1r, b1, nullptr, p_ff, NROWS, 4*CC, CC);

    // 7. FF2 + residual -> out
    gemm_tc_kernel<1,0,1,0><<<dim3(CC/128, NROWS/128), 256, GEMM_SMEM>>>(
        p_ff, p_w2r, b2, p_x1, out, NROWS, CC, 4*CC);
}

// round 14
// speedup vs baseline: 1.3294x; 1.3294x over previous
#include <cuda_runtime.h>
#include <cuda_fp16.h>
#include <math.h>
#include <stdint.h>

#define BB 2
#define TT 2048
#define CC 1024
#define HH 16
#define HS 64
#define NROWS (BB*TT)
#define LN_EPS 1e-5f

// ---------------------------------------------------------------------------
// Scratch
// ---------------------------------------------------------------------------
__device__ __half g_h   [NROWS*CC];     // LN1 out (fp16)
__device__ __half g_wqkv[3*CC*CC];      // Wt_qkv [N=3C][K=C] fp16
__device__ float  g_bqkv[3*CC];
__device__ float  g_qkv [NROWS*3*CC];   // QKV activations (fp32, feeds attn)
__device__ __half g_attn[NROWS*CC];     // attention out (fp16)
__device__ float  g_x1  [NROWS*CC];     // after attn residual (fp32)
__device__ __half g_h2  [NROWS*CC];     // LN2 out (fp16)
__device__ __half g_ff  [NROWS*4*CC];   // FF hidden (fp16)
__device__ __half g_wor [CC*CC];        // Wt_o [C][C] fp16
__device__ __half g_w1r [4*CC*CC];      // Wt_1 [4C][C] fp16
__device__ __half g_w2r [CC*4*CC];      // Wt_2 [C][4C] fp16

__device__ __forceinline__ float ex2_mufu(float y) {
    float r;
    asm("ex2.approx.ftz.f32 %0, %1;" : "=f"(r) : "f"(y));
    return r;
}
__device__ __forceinline__ float ex2_poly(float y) {
    float r = y + 12582912.f;
    int   n = __float_as_int(r);
    float t = r - 12582912.f;
    float f = y - t;
    float p = 0.00961813f;
    p = fmaf(p, f, 0.05550411f);
    p = fmaf(p, f, 0.24022651f);
    p = fmaf(p, f, 0.69314718f);
    p = fmaf(p, f, 1.0f);
    return __int_as_float(__float_as_int(p) + (n << 23));
}
__device__ __forceinline__ uint32_t pack_bf16x2(float lo, float hi) {
    uint32_t r;
    asm("cvt.rn.bf16x2.f32 %0, %1, %2;" : "=r"(r) : "f"(hi), "f"(lo));
    return r;
}
__device__ __forceinline__ void cp16(uint32_t dst, const void* src) {
    asm volatile("cp.async.cg.shared.global [%0], [%1], 16;\n"
                 :: "r"(dst), "l"(src));
}
#define CP_COMMIT() asm volatile("cp.async.commit_group;\n" ::: "memory")
#define CP_WAIT(n)  asm volatile("cp.async.wait_group %0;\n" :: "n"(n) : "memory")

// ---------------------------------------------------------------------------
// Weight transpose to fp16: W[K,N] f32 -> Wt[N,K] f16.  grid (N/64, K/32)
// ---------------------------------------------------------------------------
__global__ void transpose_w_h_kernel(const float* __restrict__ src,
                                     __half* __restrict__ dst, int K, int N) {
    __shared__ float smw[32][68];
    int n0 = blockIdx.x * 64, k0 = blockIdx.y * 32;
    int tid = threadIdx.x;
    int r = tid >> 3, c8 = (tid & 7) * 8;
    *(float4*)&smw[r][c8]     = *(const float4*)&src[(size_t)(k0 + r)*N + n0 + c8];
    *(float4*)&smw[r][c8 + 4] = *(const float4*)&src[(size_t)(k0 + r)*N + n0 + c8 + 4];
    __syncthreads();
    int nl = tid >> 2, j = tid & 3;
    __half2 h0 = __floats2half2_rn(smw[j*8+0][nl], smw[j*8+1][nl]);
    __half2 h1 = __floats2half2_rn(smw[j*8+2][nl], smw[j*8+3][nl]);
    __half2 h2 = __floats2half2_rn(smw[j*8+4][nl], smw[j*8+5][nl]);
    __half2 h3 = __floats2half2_rn(smw[j*8+6][nl], smw[j*8+7][nl]);
    __half* d = dst + (size_t)(n0 + nl)*K + k0 + j*8;
    ((__half2*)d)[0] = h0; ((__half2*)d)[1] = h1;
    ((__half2*)d)[2] = h2; ((__half2*)d)[3] = h3;
}

// QKV: Wq/Wk/Wv [H,C,HS] -> Wt_qkv [n=w*C+h*64+d][k=c] fp16.  grid (CC/32, HH)
__global__ void pack_qkv_wt_kernel(const float* __restrict__ Wq,
                                   const float* __restrict__ Wk,
                                   const float* __restrict__ Wv) {
    __shared__ float smw[32][68];
    int c0 = blockIdx.x * 32, h = blockIdx.y;
    int tid = threadIdx.x;
    int r = tid >> 3, c8 = (tid & 7) * 8;
    const float* srcs[3] = {Wq, Wk, Wv};
#pragma unroll
    for (int m = 0; m < 3; m++) {
        const float* s = srcs[m] + ((size_t)h*CC + c0)*HS;
        *(float4*)&smw[r][c8]     = *(const float4*)&s[(size_t)r*HS + c8];
        *(float4*)&smw[r][c8 + 4] = *(const float4*)&s[(size_t)r*HS + c8 + 4];
        __syncthreads();
        int nl = tid >> 2, j = tid & 3;     // nl = d (0..63)
        __half2 h0 = __floats2half2_rn(smw[j*8+0][nl], smw[j*8+1][nl]);
        __half2 h1 = __floats2half2_rn(smw[j*8+2][nl], smw[j*8+3][nl]);
        __half2 h2 = __floats2half2_rn(smw[j*8+4][nl], smw[j*8+5][nl]);
        __half2 h3 = __floats2half2_rn(smw[j*8+6][nl], smw[j*8+7][nl]);
        __half* d = g_wqkv + (size_t)(m*CC + h*HS + nl)*CC + c0 + j*8;
        ((__half2*)d)[0] = h0; ((__half2*)d)[1] = h1;
        ((__half2*)d)[2] = h2; ((__half2*)d)[3] = h3;
        __syncthreads();
    }
}

__global__ void pack_bias_kernel(const float* __restrict__ bq,
                                 const float* __restrict__ bk,
                                 const float* __restrict__ bv) {
    int e = blockIdx.x * blockDim.x + threadIdx.x;
    if (e < CC) {
        g_bqkv[e]        = bq[e];
        g_bqkv[CC + e]   = bk[e];
        g_bqkv[2*CC + e] = bv[e];
    }
}

// ---------------------------------------------------------------------------
// LayerNorm over sequence axis; fp16 output.  block (16,64), grid (CC/16, BB)
// ---------------------------------------------------------------------------
__global__ void __launch_bounds__(1024)
ln_seq_kernel(const float* __restrict__ x,
              const float* __restrict__ gamma,
              const float* __restrict__ beta,
              __half* __restrict__ out) {
    int b  = blockIdx.y;
    int tx = threadIdx.x, ty = threadIdx.y;
    int c  = blockIdx.x * 16 + tx;
    const float* xp = x   + (size_t)b*TT*CC + c;
    __half*      op = out + (size_t)b*TT*CC + c;

    float s = 0.f, sq = 0.f;
    for (int t = ty; t < TT; t += 64) {
        float v = xp[(size_t)t*CC];
        s += v; sq += v*v;
    }
    __shared__ float ssum[64][17];
    __shared__ float ssq [64][17];
    ssum[ty][tx] = s; ssq[ty][tx] = sq;
    __syncthreads();
    for (int off = 32; off > 0; off >>= 1) {
        if (ty < off) {
            ssum[ty][tx] += ssum[ty+off][tx];
            ssq [ty][tx] += ssq [ty+off][tx];
        }
        __syncthreads();
    }
    __shared__ float meanv[16], rstdv[16];
    if (ty == 0) {
        float mean = ssum[0][tx] * (1.0f / TT);
        float var  = (ssq[0][tx] - (float)TT * mean * mean) * (1.0f / (TT - 1));
        meanv[tx]  = mean;
        rstdv[tx]  = 1.0f / (sqrtf(var) + LN_EPS);
    }
    __syncthreads();
    float mean = meanv[tx], rstd = rstdv[tx];
    float g = gamma[c], bt = beta[c];
    for (int t = ty; t < TT; t += 64) {
        float v = xp[(size_t)t*CC];
        op[(size_t)t*CC] = __float2half(g * ((v - mean) * rstd) + bt);
    }
}

// ---------------------------------------------------------------------------
// fp16 tensor-core GEMM: C[M,N] = A[M,K] @ Bt[N,K]^T (+bias,+relu,+res)
// m16n8k16 fp16, fp32 accum.  128x128 tile, 8 warps (4m x 2n), warp 32x64.
// A/B smem: [row][k-pair u32] stride 20 (attention-proven layout).
// 2-stage cp.async double buffer; 2 CTAs/SM.
// ---------------------------------------------------------------------------
#define MMA_F16(d, a, b)                                                      \
    asm volatile(                                                             \
        "mma.sync.aligned.m16n8k16.row.col.f32.f16.f16.f32 "                  \
        "{%0,%1,%2,%3},{%4,%5,%6,%7},{%8,%9},{%0,%1,%2,%3};\n"                \
        : "+f"((d)[0]), "+f"((d)[1]), "+f"((d)[2]), "+f"((d)[3])              \
        : "r"((a)[0]), "r"((a)[1]), "r"((a)[2]), "r"((a)[3]),                 \
          "r"((b)[0]), "r"((b)[1]))

#define AH_U32 20                    /* row stride in u32 (16 data + 4 pad) */
#define ASZ (128*AH_U32)             /* 2560 u32 per operand per stage */
#define GEMMH_SMEM (4*ASZ*4)         /* 40960 B */

template<int DOBIAS, int DORELU, int DORES, int OUTH>
__global__ void __launch_bounds__(256, 2)
gemm_h_kernel(const __half* __restrict__ A, const __half* __restrict__ Bt,
              const float* __restrict__ bias, const float* __restrict__ res,
              void* __restrict__ Cm, int M, int N, int K) {
    extern __shared__ uint32_t smg[];
    int tid  = threadIdx.x;
    int lane = tid & 31, wid = tid >> 5;
    int wm = (wid >> 1) * 32;
    int wn = (wid & 1) * 64;
    int g  = lane >> 2;
    int tg = lane & 3;
    int m0 = blockIdx.y * 128, n0 = blockIdx.x * 128;

    float acc[2][8][4];
#pragma unroll
    for (int mf = 0; mf < 2; mf++)
#pragma unroll
        for (int nf = 0; nf < 8; nf++)
#pragma unroll
            for (int r = 0; r < 4; r++) acc[mf][nf][r] = 0.f;

    uint32_t smg_u = (uint32_t)__cvta_generic_to_shared(smg);
    int nk = K >> 5;               // K chunks of 32 halves

    // staging: per operand 512 cp16 (128 rows x 4x16B); per thread 2 each
#define STAGE_H(buf, k0)                                                      \
    do {                                                                      \
        uint32_t ab = smg_u + ((buf)*ASZ)*4;                                  \
        uint32_t bb = smg_u + ((2 + (buf))*ASZ)*4;                            \
        _Pragma("unroll")                                                     \
        for (int p = 0; p < 2; p++) {                                         \
            int idx = tid + p*256;                                            \
            int r = idx >> 2, c = idx & 3;                                    \
            cp16(ab + (r*AH_U32 + c*4)*4,                                     \
                 &A [(size_t)(m0 + r)*K + (k0) + c*8]);                       \
            cp16(bb + (r*AH_U32 + c*4)*4,                                     \
                 &Bt[(size_t)(n0 + r)*K + (k0) + c*8]);                       \
        }                                                                     \
        CP_COMMIT();                                                          \
    } while (0)

    STAGE_H(0, 0);

    for (int i = 0; i < nk; i++) {
        int buf = i & 1;
        if (i + 1 < nk) {
            STAGE_H((i + 1) & 1, (i + 1) << 5);
            CP_WAIT(1);
        } else {
            CP_WAIT(0);
        }
        __syncthreads();

        const uint32_t* As = smg + buf*ASZ;
        const uint32_t* Bs = smg + (2 + buf)*ASZ;

#pragma unroll
        for (int ks = 0; ks < 2; ks++) {
            int kk = ks * 8;                  // u32 (k-pair) offset
            uint32_t afr[2][4];
#pragma unroll
            for (int mf = 0; mf < 2; mf++) {
                int r = wm + mf*16 + g;
                afr[mf][0] = As[(r    )*AH_U32 + kk + tg    ];
                afr[mf][1] = As[(r + 8)*AH_U32 + kk + tg    ];
                afr[mf][2] = As[(r    )*AH_U32 + kk + tg + 4];
                afr[mf][3] = As[(r + 8)*AH_U32 + kk + tg + 4];
            }
#pragma unroll
            for (int nf = 0; nf < 8; nf++) {
                int n = wn + nf*8 + g;
                uint32_t bfr[2];
                bfr[0] = Bs[n*AH_U32 + kk + tg    ];
                bfr[1] = Bs[n*AH_U32 + kk + tg + 4];
#pragma unroll
                for (int mf = 0; mf < 2; mf++)
                    MMA_F16(acc[mf][nf], afr[mf], bfr);
            }
        }
        __syncthreads();
    }
#undef STAGE_H

#pragma unroll
    for (int mf = 0; mf < 2; mf++) {
#pragma unroll
        for (int nf = 0; nf < 8; nf++) {
            int r  = m0 + wm + mf*16 + g;
            int cb = n0 + wn + nf*8 + 2*tg;
            float2 v0 = make_float2(acc[mf][nf][0], acc[mf][nf][1]);
            float2 v1 = make_float2(acc[mf][nf][2], acc[mf][nf][3]);
            if (DOBIAS) {
                float2 bsv = *(const float2*)&bias[cb];
                v0.x += bsv.x; v0.y += bsv.y;
                v1.x += bsv.x; v1.y += bsv.y;
            }
            if (DORELU) {
                v0.x = fmaxf(v0.x, 0.f); v0.y = fmaxf(v0.y, 0.f);
                v1.x = fmaxf(v1.x, 0.f); v1.y = fmaxf(v1.y, 0.f);
            }
            if (DORES) {
                float2 r0 = *(const float2*)&res[(size_t)r*N + cb];
                float2 r1 = *(const float2*)&res[(size_t)(r+8)*N + cb];
                v0.x += r0.x; v0.y += r0.y;
                v1.x += r1.x; v1.y += r1.y;
            }
            if (OUTH) {
                __half* C = (__half*)Cm;
                *(__half2*)&C[(size_t)r*N + cb]     = __floats2half2_rn(v0.x, v0.y);
                *(__half2*)&C[(size_t)(r+8)*N + cb] = __floats2half2_rn(v1.x, v1.y);
            } else {
                float* C = (float*)Cm;
                *(float2*)&C[(size_t)r*N + cb]     = v0;
                *(float2*)&C[(size_t)(r+8)*N + cb] = v1;
            }
        }
    }
}

// ---------------------------------------------------------------------------
// bf16 tensor-core flash attention (verified R6; output store now fp16)
// ---------------------------------------------------------------------------
#define QS32 36
#define KS32 36
#define VS32 36
#define SM32_QS 0
#define SM32_KS (128*QS32)
#define SM32_VT (SM32_KS + 64*KS32)
#define ATTN_SMEM ((SM32_VT + 64*VS32)*4)
#define QSCALE 0.18033688f

#define MMA_BF16(d, a, b)                                                     \
    asm volatile(                                                             \
        "mma.sync.aligned.m16n8k16.row.col.f32.bf16.bf16.f32 "                \
        "{%0,%1,%2,%3},{%4,%5,%6,%7},{%8,%9},{%0,%1,%2,%3};\n"                \
        : "+f"((d)[0]), "+f"((d)[1]), "+f"((d)[2]), "+f"((d)[3])              \
        : "r"((a)[0]), "r"((a)[1]), "r"((a)[2]), "r"((a)[3]),                 \
          "r"((b)[0]), "r"((b)[1]))

__global__ void __launch_bounds__(256, 2) attn_tc_kernel() {
    extern __shared__ uint32_t smu[];
    uint32_t* Qs = smu + SM32_QS;
    uint32_t* Ks = smu + SM32_KS;
    uint32_t* Vt = smu + SM32_VT;

    int tid = threadIdx.x, lane = tid & 31, wid = tid >> 5;
    int g = lane >> 2, tg = lane & 3;
    int b = blockIdx.z, h = blockIdx.y;
    int tq0 = blockIdx.x * 128;
    int wr = wid * 16;

    const float* qbase = g_qkv + (size_t)b*TT*3*CC + (size_t)h*HS;
    const float* kbase = qbase + CC;
    const float* vbase = qbase + 2*CC;

#pragma unroll
    for (int p = 0; p < 8; p++) {
        int idx = tid + p*256;
        int r = idx >> 4, c4 = idx & 15;
        float4 v = *(const float4*)&qbase[(size_t)(tq0 + r)*3*CC + c4*4];
        Qs[r*QS32 + c4*2    ] = pack_bf16x2(v.x*QSCALE, v.y*QSCALE);
        Qs[r*QS32 + c4*2 + 1] = pack_bf16x2(v.z*QSCALE, v.w*QSCALE);
    }

    float o[8][4];
#pragma unroll
    for (int i = 0; i < 8; i++)
#pragma unroll
        for (int j = 0; j < 4; j++) o[i][j] = 0.f;
    float lsum0 = 0.f, lsum1 = 0.f;

    __syncthreads();

    for (int kt = 0; kt < TT; kt += 64) {
#pragma unroll
        for (int p = 0; p < 4; p++) {
            int idx = tid + p*256;
            int r = idx >> 4, c4 = idx & 15;
            float4 v = *(const float4*)&kbase[(size_t)(kt + r)*3*CC + c4*4];
            Ks[r*KS32 + c4*2    ] = pack_bf16x2(v.x, v.y);
            Ks[r*KS32 + c4*2 + 1] = pack_bf16x2(v.z, v.w);
        }
#pragma unroll
        for (int p = 0; p < 2; p++) {
            int idx = tid + p*256;
            int sp = idx & 31, dg = idx >> 5;
            int d0 = dg * 4;
            float4 v0 = *(const float4*)&vbase[(size_t)(kt + 2*sp    )*3*CC + d0];
            float4 v1 = *(const float4*)&vbase[(size_t)(kt + 2*sp + 1)*3*CC + d0];
            Vt[(d0    )*VS32 + sp] = pack_bf16x2(v0.x, v1.x);
            Vt[(d0 + 1)*VS32 + sp] = pack_bf16x2(v0.y, v1.y);
            Vt[(d0 + 2)*VS32 + sp] = pack_bf16x2(v0.z, v1.z);
            Vt[(d0 + 3)*VS32 + sp] = pack_bf16x2(v0.w, v1.w);
        }
        __syncthreads();

        float s[8][4];
#pragma unroll
        for (int nf = 0; nf < 8; nf++)
#pragma unroll
            for (int j = 0; j < 4; j++) s[nf][j] = 0.f;

#pragma unroll
        for (int c = 0; c < 4; c++) {
            int c8 = c * 8;
            uint32_t aq[4];
            aq[0] = Qs[(wr+g  )*QS32 + c8 + tg    ];
            aq[1] = Qs[(wr+g+8)*QS32 + c8 + tg    ];
            aq[2] = Qs[(wr+g  )*QS32 + c8 + tg + 4];
            aq[3] = Qs[(wr+g+8)*QS32 + c8 + tg + 4];
#pragma unroll
            for (int nf = 0; nf < 8; nf++) {
                uint32_t bk[2];
                bk[0] = Ks[(nf*8+g)*KS32 + c8 + tg    ];
                bk[1] = Ks[(nf*8+g)*KS32 + c8 + tg + 4];
                MMA_BF16(s[nf], aq, bk);
            }
        }

#pragma unroll
        for (int nf = 0; nf < 8; nf++) {
            if (nf < 4) {
                s[nf][0] = ex2_mufu(fminf(s[nf][0], 80.f));
                s[nf][1] = ex2_mufu(fminf(s[nf][1], 80.f));
                s[nf][2] = ex2_mufu(fminf(s[nf][2], 80.f));
                s[nf][3] = ex2_mufu(fminf(s[nf][3], 80.f));
            } else {
                s[nf][0] = ex2_poly(fminf(fmaxf(s[nf][0], -80.f), 80.f));
                s[nf][1] = ex2_poly(fminf(fmaxf(s[nf][1], -80.f), 80.f));
                s[nf][2] = ex2_poly(fminf(fmaxf(s[nf][2], -80.f), 80.f));
                s[nf][3] = ex2_poly(fminf(fmaxf(s[nf][3], -80.f), 80.f));
            }
            lsum0 += s[nf][0] + s[nf][1];
            lsum1 += s[nf][2] + s[nf][3];
        }

#pragma unroll
        for (int j = 0; j < 4; j++) {
            uint32_t ap[4];
            ap[0] = pack_bf16x2(s[2*j  ][0], s[2*j  ][1]);
            ap[1] = pack_bf16x2(s[2*j  ][2], s[2*j  ][3]);
            ap[2] = pack_bf16x2(s[2*j+1][0], s[2*j+1][1]);
            ap[3] = pack_bf16x2(s[2*j+1][2], s[2*j+1][3]);
            int c8 = j * 8;
#pragma unroll
            for (int nf = 0; nf < 8; nf++) {
                uint32_t bv[2];
                bv[0] = Vt[(nf*8+g)*VS32 + c8 + tg    ];
                bv[1] = Vt[(nf*8+g)*VS32 + c8 + tg + 4];
                MMA_BF16(o[nf], ap, bv);
            }
        }
        __syncthreads();
    }

    lsum0 += __shfl_xor_sync(0xffffffffu, lsum0, 1);
    lsum0 += __shfl_xor_sync(0xffffffffu, lsum0, 2);
    lsum1 += __shfl_xor_sync(0xffffffffu, lsum1, 1);
    lsum1 += __shfl_xor_sync(0xffffffffu, lsum1, 2);
    float inv0 = 1.0f / lsum0, inv1 = 1.0f / lsum1;

    int row0 = b*TT + tq0 + wr + g;
#pragma unroll
    for (int nf = 0; nf < 8; nf++) {
        int col = h*HS + nf*8 + 2*tg;
        *(__half2*)&g_attn[(size_t)row0*CC + col] =
            __floats2half2_rn(o[nf][0]*inv0, o[nf][1]*inv0);
        *(__half2*)&g_attn[(size_t)(row0+8)*CC + col] =
            __floats2half2_rn(o[nf][2]*inv1, o[nf][3]*inv1);
    }
}

// ---------------------------------------------------------------------------
// Launch
// ---------------------------------------------------------------------------
extern "C" void kernel_launch(void* const* d_in, const int* in_sizes, int n_in,
                              void* d_out, int out_size) {
    const float* x      = (const float*)d_in[0];
    const float* Wq     = (const float*)d_in[1];
    const float* bq     = (const float*)d_in[2];
    const float* Wk     = (const float*)d_in[3];
    const float* bk     = (const float*)d_in[4];
    const float* Wv     = (const float*)d_in[5];
    const float* bv     = (const float*)d_in[6];
    const float* Wo     = (const float*)d_in[7];
    const float* bo     = (const float*)d_in[8];
    const float* W1     = (const float*)d_in[9];
    const float* b1     = (const float*)d_in[10];
    const float* W2     = (const float*)d_in[11];
    const float* b2     = (const float*)d_in[12];
    const float* gamma1 = (const float*)d_in[13];
    const float* beta1  = (const float*)d_in[14];
    const float* gamma2 = (const float*)d_in[15];
    const float* beta2  = (const float*)d_in[16];
    float* out = (float*)d_out;

    __half *p_h, *p_wqkv, *p_attn, *p_h2, *p_ff, *p_wor, *p_w1r, *p_w2r;
    float  *p_bqkv, *p_qkv, *p_x1;
    cudaGetSymbolAddress((void**)&p_h,    g_h);
    cudaGetSymbolAddress((void**)&p_wqkv, g_wqkv);
    cudaGetSymbolAddress((void**)&p_bqkv, g_bqkv);
    cudaGetSymbolAddress((void**)&p_qkv,  g_qkv);
    cudaGetSymbolAddress((void**)&p_attn, g_attn);
    cudaGetSymbolAddress((void**)&p_x1,   g_x1);
    cudaGetSymbolAddress((void**)&p_h2,   g_h2);
    cudaGetSymbolAddress((void**)&p_ff,   g_ff);
    cudaGetSymbolAddress((void**)&p_wor,  g_wor);
    cudaGetSymbolAddress((void**)&p_w1r,  g_w1r);
    cudaGetSymbolAddress((void**)&p_w2r,  g_w2r);

    cudaFuncSetAttribute(attn_tc_kernel,
                         cudaFuncAttributeMaxDynamicSharedMemorySize, ATTN_SMEM);
    cudaFuncSetAttribute(gemm_h_kernel<1,0,0,0>,
                         cudaFuncAttributeMaxDynamicSharedMemorySize, GEMMH_SMEM);
    cudaFuncSetAttribute(gemm_h_kernel<1,0,1,0>,
                         cudaFuncAttributeMaxDynamicSharedMemorySize, GEMMH_SMEM);
    cudaFuncSetAttribute(gemm_h_kernel<1,1,0,1>,
                         cudaFuncAttributeMaxDynamicSharedMemorySize, GEMMH_SMEM);

    // 0. weight prep: transposed fp16 copies
    pack_qkv_wt_kernel<<<dim3(CC/32, HH), 256>>>(Wq, Wk, Wv);
    pack_bias_kernel<<<(CC + 255)/256, 256>>>(bq, bk, bv);
    transpose_w_h_kernel<<<dim3(CC/64,   CC/32),   256>>>(Wo, p_wor, CC,   CC);
    transpose_w_h_kernel<<<dim3(4*CC/64, CC/32),   256>>>(W1, p_w1r, CC,   4*CC);
    transpose_w_h_kernel<<<dim3(CC/64,   4*CC/32), 256>>>(W2, p_w2r, 4*CC, CC);

    // 1. LN1 (fp16 out)
    ln_seq_kernel<<<dim3(CC/16, BB), dim3(16, 64)>>>(x, gamma1, beta1, p_h);

    // 2. QKV GEMM: [4096,1024] @ [1024,3072] -> fp32 g_qkv
    gemm_h_kernel<1,0,0,0><<<dim3(3*CC/128, NROWS/128), 256, GEMMH_SMEM>>>(
        p_h, p_wqkv, p_bqkv, nullptr, p_qkv, NROWS, 3*CC, CC);

    // 3. attention (bf16 flash, fp16 out)
    attn_tc_kernel<<<dim3(TT/128, HH, BB), 256, ATTN_SMEM>>>();

    // 4. output projection + residual -> fp32 x1
    gemm_h_kernel<1,0,1,0><<<dim3(CC/128, NROWS/128), 256, GEMMH_SMEM>>>(
        p_attn, p_wor, bo, x, p_x1, NROWS, CC, CC);

    // 5. LN2 (fp16 out)
    ln_seq_kernel<<<dim3(CC/16, BB), dim3(16, 64)>>>(p_x1, gamma2, beta2, p_h2);

    // 6. FF1 + relu -> fp16 g_ff
    gemm_h_kernel<1,1,0,1><<<dim3(4*CC/128, NROWS/128), 256, GEMMH_SMEM>>>(
        p_h2, p_w1r, b1, nullptr, p_ff, NROWS, 4*CC, CC);

    // 7. FF2 + residual -> fp32 out
    gemm_h_kernel<1,0,1,0><<<dim3(CC/128, NROWS/128), 256, GEMMH_SMEM>>>(
        p_ff, p_w2r, b2, p_x1, out, NROWS, CC, 4*CC);
}

// round 15
// speedup vs baseline: 1.3652x; 1.0269x over previous
#include <cuda_runtime.h>
#include <cuda_fp16.h>
#include <cuda_bf16.h>
#include <math.h>
#include <stdint.h>

#define BB 2
#define TT 2048
#define CC 1024
#define HH 16
#define HS 64
#define NROWS (BB*TT)
#define LN_EPS 1e-5f
#define QSCALE 0.18033688f    /* 0.125 * log2(e), folded into Wq/bq */

// ---------------------------------------------------------------------------
// Scratch
// ---------------------------------------------------------------------------
__device__ __half g_h   [NROWS*CC];     // LN1 out (fp16)
__device__ __half g_wqkv[3*CC*CC];      // Wt_qkv [N=3C][K=C] fp16 (Wq pre-scaled)
__device__ float  g_bqkv[3*CC];         // (bq pre-scaled)
__device__ __nv_bfloat16 g_qkv[NROWS*3*CC];  // QKV activations (bf16)
__device__ __half g_attn[NROWS*CC];     // attention out (fp16)
__device__ float  g_x1  [NROWS*CC];     // after attn residual (fp32)
__device__ __half g_h2  [NROWS*CC];     // LN2 out (fp16)
__device__ __half g_ff  [NROWS*4*CC];   // FF hidden (fp16)
__device__ __half g_wor [CC*CC];        // Wt_o [C][C] fp16
__device__ __half g_w1r [4*CC*CC];      // Wt_1 [4C][C] fp16
__device__ __half g_w2r [CC*4*CC];      // Wt_2 [C][4C] fp16

__device__ __forceinline__ float ex2_mufu(float y) {
    float r;
    asm("ex2.approx.ftz.f32 %0, %1;" : "=f"(r) : "f"(y));
    return r;
}
__device__ __forceinline__ float ex2_poly(float y) {
    float r = y + 12582912.f;
    int   n = __float_as_int(r);
    float t = r - 12582912.f;
    float f = y - t;
    float p = 0.00961813f;
    p = fmaf(p, f, 0.05550411f);
    p = fmaf(p, f, 0.24022651f);
    p = fmaf(p, f, 0.69314718f);
    p = fmaf(p, f, 1.0f);
    return __int_as_float(__float_as_int(p) + (n << 23));
}
__device__ __forceinline__ uint32_t pack_bf16x2(float lo, float hi) {
    uint32_t r;
    asm("cvt.rn.bf16x2.f32 %0, %1, %2;" : "=r"(r) : "f"(hi), "f"(lo));
    return r;
}
__device__ __forceinline__ uint32_t prmt(uint32_t a, uint32_t b, uint32_t sel) {
    uint32_t d;
    asm("prmt.b32 %0, %1, %2, %3;" : "=r"(d) : "r"(a), "r"(b), "r"(sel));
    return d;
}
__device__ __forceinline__ void cp16(uint32_t dst, const void* src) {
    asm volatile("cp.async.cg.shared.global [%0], [%1], 16;\n"
                 :: "r"(dst), "l"(src));
}
#define CP_COMMIT() asm volatile("cp.async.commit_group;\n" ::: "memory")
#define CP_WAIT(n)  asm volatile("cp.async.wait_group %0;\n" :: "n"(n) : "memory")

// ---------------------------------------------------------------------------
// Weight transpose to fp16: W[K,N] f32 -> Wt[N,K] f16.  grid (N/64, K/32)
// ---------------------------------------------------------------------------
__global__ void transpose_w_h_kernel(const float* __restrict__ src,
                                     __half* __restrict__ dst, int K, int N) {
    __shared__ float smw[32][68];
    int n0 = blockIdx.x * 64, k0 = blockIdx.y * 32;
    int tid = threadIdx.x;
    int r = tid >> 3, c8 = (tid & 7) * 8;
    *(float4*)&smw[r][c8]     = *(const float4*)&src[(size_t)(k0 + r)*N + n0 + c8];
    *(float4*)&smw[r][c8 + 4] = *(const float4*)&src[(size_t)(k0 + r)*N + n0 + c8 + 4];
    __syncthreads();
    int nl = tid >> 2, j = tid & 3;
    __half2 h0 = __floats2half2_rn(smw[j*8+0][nl], smw[j*8+1][nl]);
    __half2 h1 = __floats2half2_rn(smw[j*8+2][nl], smw[j*8+3][nl]);
    __half2 h2 = __floats2half2_rn(smw[j*8+4][nl], smw[j*8+5][nl]);
    __half2 h3 = __floats2half2_rn(smw[j*8+6][nl], smw[j*8+7][nl]);
    __half* d = dst + (size_t)(n0 + nl)*K + k0 + j*8;
    ((__half2*)d)[0] = h0; ((__half2*)d)[1] = h1;
    ((__half2*)d)[2] = h2; ((__half2*)d)[3] = h3;
}

// QKV: Wq/Wk/Wv [H,C,HS] -> Wt_qkv [n][k] fp16; Wq scaled by QSCALE.
__global__ void pack_qkv_wt_kernel(const float* __restrict__ Wq,
                                   const float* __restrict__ Wk,
                                   const float* __restrict__ Wv) {
    __shared__ float smw[32][68];
    int c0 = blockIdx.x * 32, h = blockIdx.y;
    int tid = threadIdx.x;
    int r = tid >> 3, c8 = (tid & 7) * 8;
    const float* srcs[3] = {Wq, Wk, Wv};
#pragma unroll
    for (int m = 0; m < 3; m++) {
        float sc = (m == 0) ? QSCALE : 1.0f;
        const float* s = srcs[m] + ((size_t)h*CC + c0)*HS;
        *(float4*)&smw[r][c8]     = *(const float4*)&s[(size_t)r*HS + c8];
        *(float4*)&smw[r][c8 + 4] = *(const float4*)&s[(size_t)r*HS + c8 + 4];
        __syncthreads();
        int nl = tid >> 2, j = tid & 3;
        __half2 h0 = __floats2half2_rn(smw[j*8+0][nl]*sc, smw[j*8+1][nl]*sc);
        __half2 h1 = __floats2half2_rn(smw[j*8+2][nl]*sc, smw[j*8+3][nl]*sc);
        __half2 h2 = __floats2half2_rn(smw[j*8+4][nl]*sc, smw[j*8+5][nl]*sc);
        __half2 h3 = __floats2half2_rn(smw[j*8+6][nl]*sc, smw[j*8+7][nl]*sc);
        __half* d = g_wqkv + (size_t)(m*CC + h*HS + nl)*CC + c0 + j*8;
        ((__half2*)d)[0] = h0; ((__half2*)d)[1] = h1;
        ((__half2*)d)[2] = h2; ((__half2*)d)[3] = h3;
        __syncthreads();
    }
}

__global__ void pack_bias_kernel(const float* __restrict__ bq,
                                 const float* __restrict__ bk,
                                 const float* __restrict__ bv) {
    int e = blockIdx.x * blockDim.x + threadIdx.x;
    if (e < CC) {
        g_bqkv[e]        = bq[e] * QSCALE;
        g_bqkv[CC + e]   = bk[e];
        g_bqkv[2*CC + e] = bv[e];
    }
}

// ---------------------------------------------------------------------------
// LayerNorm over sequence axis; fp16 output.
// ---------------------------------------------------------------------------
__global__ void __launch_bounds__(1024)
ln_seq_kernel(const float* __restrict__ x,
              const float* __restrict__ gamma,
              const float* __restrict__ beta,
              __half* __restrict__ out) {
    int b  = blockIdx.y;
    int tx = threadIdx.x, ty = threadIdx.y;
    int c  = blockIdx.x * 16 + tx;
    const float* xp = x   + (size_t)b*TT*CC + c;
    __half*      op = out + (size_t)b*TT*CC + c;

    float s = 0.f, sq = 0.f;
    for (int t = ty; t < TT; t += 64) {
        float v = xp[(size_t)t*CC];
        s += v; sq += v*v;
    }
    __shared__ float ssum[64][17];
    __shared__ float ssq [64][17];
    ssum[ty][tx] = s; ssq[ty][tx] = sq;
    __syncthreads();
    for (int off = 32; off > 0; off >>= 1) {
        if (ty < off) {
            ssum[ty][tx] += ssum[ty+off][tx];
            ssq [ty][tx] += ssq [ty+off][tx];
        }
        __syncthreads();
    }
    __shared__ float meanv[16], rstdv[16];
    if (ty == 0) {
        float mean = ssum[0][tx] * (1.0f / TT);
        float var  = (ssq[0][tx] - (float)TT * mean * mean) * (1.0f / (TT - 1));
        meanv[tx]  = mean;
        rstdv[tx]  = 1.0f / (sqrtf(var) + LN_EPS);
    }
    __syncthreads();
    float mean = meanv[tx], rstd = rstdv[tx];
    float g = gamma[c], bt = beta[c];
    for (int t = ty; t < TT; t += 64) {
        float v = xp[(size_t)t*CC];
        op[(size_t)t*CC] = __float2half(g * ((v - mean) * rstd) + bt);
    }
}

// ---------------------------------------------------------------------------
// fp16 GEMM m16n8k16, 128x128 tile, k-chunk 64 halves, 2-stage cp.async.
// OUT: 0=f32, 1=f16, 2=bf16
// ---------------------------------------------------------------------------
#define MMA_F16(d, a, b)                                                      \
    asm volatile(                                                             \
        "mma.sync.aligned.m16n8k16.row.col.f32.f16.f16.f32 "                  \
        "{%0,%1,%2,%3},{%4,%5,%6,%7},{%8,%9},{%0,%1,%2,%3};\n"                \
        : "+f"((d)[0]), "+f"((d)[1]), "+f"((d)[2]), "+f"((d)[3])              \
        : "r"((a)[0]), "r"((a)[1]), "r"((a)[2]), "r"((a)[3]),                 \
          "r"((b)[0]), "r"((b)[1]))

#define AH_U32 36                    /* 32 data u32 (64 halves) + 4 pad */
#define ASZ (128*AH_U32)
#define GEMMH_SMEM (4*ASZ*4)         /* 73728 B */

template<int DOBIAS, int DORELU, int DORES, int OUT>
__global__ void __launch_bounds__(256, 2)
gemm_h_kernel(const __half* __restrict__ A, const __half* __restrict__ Bt,
              const float* __restrict__ bias, const float* __restrict__ res,
              void* __restrict__ Cm, int M, int N, int K) {
    extern __shared__ uint32_t smg[];
    int tid  = threadIdx.x;
    int lane = tid & 31, wid = tid >> 5;
    int wm = (wid >> 1) * 32;
    int wn = (wid & 1) * 64;
    int g  = lane >> 2;
    int tg = lane & 3;
    int m0 = blockIdx.y * 128, n0 = blockIdx.x * 128;

    float acc[2][8][4];
#pragma unroll
    for (int mf = 0; mf < 2; mf++)
#pragma unroll
        for (int nf = 0; nf < 8; nf++)
#pragma unroll
            for (int r = 0; r < 4; r++) acc[mf][nf][r] = 0.f;

    uint32_t smg_u = (uint32_t)__cvta_generic_to_shared(smg);
    int nk = K >> 6;               // K chunks of 64 halves

#define STAGE_H(buf, k0)                                                      \
    do {                                                                      \
        uint32_t ab = smg_u + ((buf)*ASZ)*4;                                  \
        uint32_t bb = smg_u + ((2 + (buf))*ASZ)*4;                            \
        _Pragma("unroll")                                                     \
        for (int p = 0; p < 4; p++) {                                         \
            int idx = tid + p*256;                                            \
            int r = idx >> 3, c = idx & 7;                                    \
            cp16(ab + (r*AH_U32 + c*4)*4,                                     \
                 &A [(size_t)(m0 + r)*K + (k0) + c*8]);                       \
            cp16(bb + (r*AH_U32 + c*4)*4,                                     \
                 &Bt[(size_t)(n0 + r)*K + (k0) + c*8]);                       \
        }                                                                     \
        CP_COMMIT();                                                          \
    } while (0)

    STAGE_H(0, 0);

    for (int i = 0; i < nk; i++) {
        int buf = i & 1;
        if (i + 1 < nk) {
            STAGE_H((i + 1) & 1, (i + 1) << 6);
            CP_WAIT(1);
        } else {
            CP_WAIT(0);
        }
        __syncthreads();

        const uint32_t* As = smg + buf*ASZ;
        const uint32_t* Bs = smg + (2 + buf)*ASZ;

#pragma unroll
        for (int ks = 0; ks < 4; ks++) {
            int kk = ks * 8;                  // u32 (k-pair) offset
            uint32_t afr[2][4];
#pragma unroll
            for (int mf = 0; mf < 2; mf++) {
                int r = wm + mf*16 + g;
                afr[mf][0] = As[(r    )*AH_U32 + kk + tg    ];
                afr[mf][1] = As[(r + 8)*AH_U32 + kk + tg    ];
                afr[mf][2] = As[(r    )*AH_U32 + kk + tg + 4];
                afr[mf][3] = As[(r + 8)*AH_U32 + kk + tg + 4];
            }
#pragma unroll
            for (int nf = 0; nf < 8; nf++) {
                int n = wn + nf*8 + g;
                uint32_t bfr[2];
                bfr[0] = Bs[n*AH_U32 + kk + tg    ];
                bfr[1] = Bs[n*AH_U32 + kk + tg + 4];
#pragma unroll
                for (int mf = 0; mf < 2; mf++)
                    MMA_F16(acc[mf][nf], afr[mf], bfr);
            }
        }
        __syncthreads();
    }
#undef STAGE_H

#pragma unroll
    for (int mf = 0; mf < 2; mf++) {
#pragma unroll
        for (int nf = 0; nf < 8; nf++) {
            int r  = m0 + wm + mf*16 + g;
            int cb = n0 + wn + nf*8 + 2*tg;
            float2 v0 = make_float2(acc[mf][nf][0], acc[mf][nf][1]);
            float2 v1 = make_float2(acc[mf][nf][2], acc[mf][nf][3]);
            if (DOBIAS) {
                float2 bsv = *(const float2*)&bias[cb];
                v0.x += bsv.x; v0.y += bsv.y;
                v1.x += bsv.x; v1.y += bsv.y;
            }
            if (DORELU) {
                v0.x = fmaxf(v0.x, 0.f); v0.y = fmaxf(v0.y, 0.f);
                v1.x = fmaxf(v1.x, 0.f); v1.y = fmaxf(v1.y, 0.f);
            }
            if (DORES) {
                float2 r0 = *(const float2*)&res[(size_t)r*N + cb];
                float2 r1 = *(const float2*)&res[(size_t)(r+8)*N + cb];
                v0.x += r0.x; v0.y += r0.y;
                v1.x += r1.x; v1.y += r1.y;
            }
            if (OUT == 1) {
                __half* C = (__half*)Cm;
                *(__half2*)&C[(size_t)r*N + cb]     = __floats2half2_rn(v0.x, v0.y);
                *(__half2*)&C[(size_t)(r+8)*N + cb] = __floats2half2_rn(v1.x, v1.y);
            } else if (OUT == 2) {
                uint32_t* C = (uint32_t*)Cm;
                C[((size_t)r*N + cb) >> 1]     = pack_bf16x2(v0.x, v0.y);
                C[((size_t)(r+8)*N + cb) >> 1] = pack_bf16x2(v1.x, v1.y);
            } else {
                float* C = (float*)Cm;
                *(float2*)&C[(size_t)r*N + cb]     = v0;
                *(float2*)&C[(size_t)(r+8)*N + cb] = v1;
            }
        }
    }
}

// ---------------------------------------------------------------------------
// bf16 flash attention; inputs now bf16 (raw-copy staging, Q pre-scaled).
// ---------------------------------------------------------------------------
#define QS32 36
#define KS32 36
#define VS32 36
#define SM32_QS 0
#define SM32_KS (128*QS32)
#define SM32_VT (SM32_KS + 64*KS32)
#define ATTN_SMEM ((SM32_VT + 64*VS32)*4)

#define MMA_BF16(d, a, b)                                                     \
    asm volatile(                                                             \
        "mma.sync.aligned.m16n8k16.row.col.f32.bf16.bf16.f32 "                \
        "{%0,%1,%2,%3},{%4,%5,%6,%7},{%8,%9},{%0,%1,%2,%3};\n"                \
        : "+f"((d)[0]), "+f"((d)[1]), "+f"((d)[2]), "+f"((d)[3])              \
        : "r"((a)[0]), "r"((a)[1]), "r"((a)[2]), "r"((a)[3]),                 \
          "r"((b)[0]), "r"((b)[1]))

__global__ void __launch_bounds__(256, 2) attn_tc_kernel() {
    extern __shared__ uint32_t smu[];
    uint32_t* Qs = smu + SM32_QS;
    uint32_t* Ks = smu + SM32_KS;
    uint32_t* Vt = smu + SM32_VT;

    int tid = threadIdx.x, lane = tid & 31, wid = tid >> 5;
    int g = lane >> 2, tg = lane & 3;
    int b = blockIdx.z, h = blockIdx.y;
    int tq0 = blockIdx.x * 128;
    int wr = wid * 16;

    const __nv_bfloat16* qbase = g_qkv + (size_t)b*TT*3*CC + (size_t)h*HS;
    const __nv_bfloat16* kbase = qbase + CC;
    const __nv_bfloat16* vbase = qbase + 2*CC;

    // stage Q: raw copy (already scaled)
#pragma unroll
    for (int p = 0; p < 4; p++) {
        int idx = tid + p*256;            // 1024 = 128 rows x 8 16B-chunks
        int r = idx >> 3, c = idx & 7;
        uint4 v = *(const uint4*)&qbase[(size_t)(tq0 + r)*3*CC + c*8];
        *(uint4*)&Qs[r*QS32 + c*4] = v;
    }

    float o[8][4];
#pragma unroll
    for (int i = 0; i < 8; i++)
#pragma unroll
        for (int j = 0; j < 4; j++) o[i][j] = 0.f;
    float lsum0 = 0.f, lsum1 = 0.f;

    __syncthreads();

    for (int kt = 0; kt < TT; kt += 64) {
        // stage K: raw copy
#pragma unroll
        for (int p = 0; p < 2; p++) {
            int idx = tid + p*256;        // 512 = 64 rows x 8
            int r = idx >> 3, c = idx & 7;
            uint4 v = *(const uint4*)&kbase[(size_t)(kt + r)*3*CC + c*8];
            *(uint4*)&Ks[r*KS32 + c*4] = v;
        }
        // stage V transposed via prmt pair-interleave
#pragma unroll
        for (int p = 0; p < 4; p++) {
            int idx = tid + p*256;        // 1024 = 32 sp x 32 dg
            int sp = idx & 31, dg = idx >> 5;
            uint32_t a = *(const uint32_t*)&vbase[(size_t)(kt + 2*sp    )*3*CC + dg*2];
            uint32_t c2 = *(const uint32_t*)&vbase[(size_t)(kt + 2*sp + 1)*3*CC + dg*2];
            Vt[(2*dg    )*VS32 + sp] = prmt(a, c2, 0x5410);
            Vt[(2*dg + 1)*VS32 + sp] = prmt(a, c2, 0x7632);
        }
        __syncthreads();

        float s[8][4];
#pragma unroll
        for (int nf = 0; nf < 8; nf++)
#pragma unroll
            for (int j = 0; j < 4; j++) s[nf][j] = 0.f;

#pragma unroll
        for (int c = 0; c < 4; c++) {
            int c8 = c * 8;
            uint32_t aq[4];
            aq[0] = Qs[(wr+g  )*QS32 + c8 + tg    ];
            aq[1] = Qs[(wr+g+8)*QS32 + c8 + tg    ];
            aq[2] = Qs[(wr+g  )*QS32 + c8 + tg + 4];
            aq[3] = Qs[(wr+g+8)*QS32 + c8 + tg + 4];
#pragma unroll
            for (int nf = 0; nf < 8; nf++) {
                uint32_t bk[2];
                bk[0] = Ks[(nf*8+g)*KS32 + c8 + tg    ];
                bk[1] = Ks[(nf*8+g)*KS32 + c8 + tg + 4];
                MMA_BF16(s[nf], aq, bk);
            }
        }

#pragma unroll
        for (int nf = 0; nf < 8; nf++) {
            if (nf < 4) {
                s[nf][0] = ex2_mufu(fminf(s[nf][0], 80.f));
                s[nf][1] = ex2_mufu(fminf(s[nf][1], 80.f));
                s[nf][2] = ex2_mufu(fminf(s[nf][2], 80.f));
                s[nf][3] = ex2_mufu(fminf(s[nf][3], 80.f));
            } else {
                s[nf][0] = ex2_poly(fminf(fmaxf(s[nf][0], -80.f), 80.f));
                s[nf][1] = ex2_poly(fminf(fmaxf(s[nf][1], -80.f), 80.f));
                s[nf][2] = ex2_poly(fminf(fmaxf(s[nf][2], -80.f), 80.f));
                s[nf][3] = ex2_poly(fminf(fmaxf(s[nf][3], -80.f), 80.f));
            }
            lsum0 += s[nf][0] + s[nf][1];
            lsum1 += s[nf][2] + s[nf][3];
        }

#pragma unroll
        for (int j = 0; j < 4; j++) {
            uint32_t ap[4];
            ap[0] = pack_bf16x2(s[2*j  ][0], s[2*j  ][1]);
            ap[1] = pack_bf16x2(s[2*j  ][2], s[2*j  ][3]);
            ap[2] = pack_bf16x2(s[2*j+1][0], s[2*j+1][1]);
            ap[3] = pack_bf16x2(s[2*j+1][2], s[2*j+1][3]);
            int c8 = j * 8;
#pragma unroll
            for (int nf = 0; nf < 8; nf++) {
                uint32_t bv[2];
                bv[0] = Vt[(nf*8+g)*VS32 + c8 + tg    ];
                bv[1] = Vt[(nf*8+g)*VS32 + c8 + tg + 4];
                MMA_BF16(o[nf], ap, bv);
            }
        }
        __syncthreads();
    }

    lsum0 += __shfl_xor_sync(0xffffffffu, lsum0, 1);
    lsum0 += __shfl_xor_sync(0xffffffffu, lsum0, 2);
    lsum1 += __shfl_xor_sync(0xffffffffu, lsum1, 1);
    lsum1 += __shfl_xor_sync(0xffffffffu, lsum1, 2);
    float inv0 = 1.0f / lsum0, inv1 = 1.0f / lsum1;

    int row0 = b*TT + tq0 + wr + g;
#pragma unroll
    for (int nf = 0; nf < 8; nf++) {
        int col = h*HS + nf*8 + 2*tg;
        *(__half2*)&g_attn[(size_t)row0*CC + col] =
            __floats2half2_rn(o[nf][0]*inv0, o[nf][1]*inv0);
        *(__half2*)&g_attn[(size_t)(row0+8)*CC + col] =
            __floats2half2_rn(o[nf][2]*inv1, o[nf][3]*inv1);
    }
}

// ---------------------------------------------------------------------------
// Launch
// ---------------------------------------------------------------------------
extern "C" void kernel_launch(void* const* d_in, const int* in_sizes, int n_in,
                              void* d_out, int out_size) {
    const float* x      = (const float*)d_in[0];
    const float* Wq     = (const float*)d_in[1];
    const float* bq     = (const float*)d_in[2];
    const float* Wk     = (const float*)d_in[3];
    const float* bk     = (const float*)d_in[4];
    const float* Wv     = (const float*)d_in[5];
    const float* bv     = (const float*)d_in[6];
    const float* Wo     = (const float*)d_in[7];
    const float* bo     = (const float*)d_in[8];
    const float* W1     = (const float*)d_in[9];
    const float* b1     = (const float*)d_in[10];
    const float* W2     = (const float*)d_in[11];
    const float* b2     = (const float*)d_in[12];
    const float* gamma1 = (const float*)d_in[13];
    const float* beta1  = (const float*)d_in[14];
    const float* gamma2 = (const float*)d_in[15];
    const float* beta2  = (const float*)d_in[16];
    float* out = (float*)d_out;

    __half *p_h, *p_wqkv, *p_attn, *p_h2, *p_ff, *p_wor, *p_w1r, *p_w2r;
    float  *p_bqkv, *p_x1;
    __nv_bfloat16* p_qkv;
    cudaGetSymbolAddress((void**)&p_h,    g_h);
    cudaGetSymbolAddress((void**)&p_wqkv, g_wqkv);
    cudaGetSymbolAddress((void**)&p_bqkv, g_bqkv);
    cudaGetSymbolAddress((void**)&p_qkv,  g_qkv);
    cudaGetSymbolAddress((void**)&p_attn, g_attn);
    cudaGetSymbolAddress((void**)&p_x1,   g_x1);
    cudaGetSymbolAddress((void**)&p_h2,   g_h2);
    cudaGetSymbolAddress((void**)&p_ff,   g_ff);
    cudaGetSymbolAddress((void**)&p_wor,  g_wor);
    cudaGetSymbolAddress((void**)&p_w1r,  g_w1r);
    cudaGetSymbolAddress((void**)&p_w2r,  g_w2r);

    cudaFuncSetAttribute(attn_tc_kernel,
                         cudaFuncAttributeMaxDynamicSharedMemorySize, ATTN_SMEM);
    cudaFuncSetAttribute(gemm_h_kernel<1,0,0,2>,
                         cudaFuncAttributeMaxDynamicSharedMemorySize, GEMMH_SMEM);
    cudaFuncSetAttribute(gemm_h_kernel<1,0,1,0>,
                         cudaFuncAttributeMaxDynamicSharedMemorySize, GEMMH_SMEM);
    cudaFuncSetAttribute(gemm_h_kernel<1,1,0,1>,
                         cudaFuncAttributeMaxDynamicSharedMemorySize, GEMMH_SMEM);

    // 0. weight prep
    pack_qkv_wt_kernel<<<dim3(CC/32, HH), 256>>>(Wq, Wk, Wv);
    pack_bias_kernel<<<(CC + 255)/256, 256>>>(bq, bk, bv);
    transpose_w_h_kernel<<<dim3(CC/64,   CC/32),   256>>>(Wo, p_wor, CC,   CC);
    transpose_w_h_kernel<<<dim3(4*CC/64, CC/32),   256>>>(W1, p_w1r, CC,   4*CC);
    transpose_w_h_kernel<<<dim3(CC/64,   4*CC/32), 256>>>(W2, p_w2r, 4*CC, CC);

    // 1. LN1 (fp16 out)
    ln_seq_kernel<<<dim3(CC/16, BB), dim3(16, 64)>>>(x, gamma1, beta1, p_h);

    // 2. QKV GEMM -> bf16 g_qkv (Q pre-scaled via weights)
    gemm_h_kernel<1,0,0,2><<<dim3(3*CC/128, NROWS/128), 256, GEMMH_SMEM>>>(
        p_h, p_wqkv, p_bqkv, nullptr, p_qkv, NROWS, 3*CC, CC);

    // 3. attention (bf16 in, fp16 out)
    attn_tc_kernel<<<dim3(TT/128, HH, BB), 256, ATTN_SMEM>>>();

    // 4. output projection + residual -> fp32 x1
    gemm_h_kernel<1,0,1,0><<<dim3(CC/128, NROWS/128), 256, GEMMH_SMEM>>>(
        p_attn, p_wor, bo, x, p_x1, NROWS, CC, CC);

    // 5. LN2 (fp16 out)
    ln_seq_kernel<<<dim3(CC/16, BB), dim3(16, 64)>>>(p_x1, gamma2, beta2, p_h2);

    // 6. FF1 + relu -> fp16 g_ff
    gemm_h_kernel<1,1,0,1><<<dim3(4*CC/128, NROWS/128), 256, GEMMH_SMEM>>>(
        p_h2, p_w1r, b1, nullptr, p_ff, NROWS, 4*CC, CC);

    // 7. FF2 + residual -> fp32 out
    gemm_h_kernel<1,0,1,0><<<dim3(CC/128, NROWS/128), 256, GEMMH_SMEM>>>(
        p_ff, p_w2r, b2, p_x1, out, NROWS, CC, 4*CC);
}

// round 16
// speedup vs baseline: 1.7610x; 1.2900x over previous
#include <cuda_runtime.h>
#include <cuda_fp16.h>
#include <cuda_bf16.h>
#include <math.h>
#include <stdint.h>

#define BB 2
#define TT 2048
#define CC 1024
#define HH 16
#define HS 64
#define NROWS (BB*TT)
#define LN_EPS 1e-5f
#define QSCALE 0.18033688f    /* 0.125 * log2(e), folded into Wq/bq */

// ---------------------------------------------------------------------------
// Scratch
// ---------------------------------------------------------------------------
__device__ __half g_h   [NROWS*CC];
__device__ __half g_wqkv[3*CC*CC];
__device__ float  g_bqkv[3*CC];
__device__ __nv_bfloat16 g_qkv[NROWS*3*CC];
__device__ __half g_attn[NROWS*CC];
__device__ float  g_x1  [NROWS*CC];
__device__ __half g_h2  [NROWS*CC];
__device__ __half g_ff  [NROWS*4*CC];
__device__ __half g_wor [CC*CC];
__device__ __half g_w1r [4*CC*CC];
__device__ __half g_w2r [CC*4*CC];

__device__ __forceinline__ float ex2_mufu(float y) {
    float r;
    asm("ex2.approx.ftz.f32 %0, %1;" : "=f"(r) : "f"(y));
    return r;
}
__device__ __forceinline__ float ex2_poly(float y) {
    float r = y + 12582912.f;
    int   n = __float_as_int(r);
    float t = r - 12582912.f;
    float f = y - t;
    float p = 0.00961813f;
    p = fmaf(p, f, 0.05550411f);
    p = fmaf(p, f, 0.24022651f);
    p = fmaf(p, f, 0.69314718f);
    p = fmaf(p, f, 1.0f);
    return __int_as_float(__float_as_int(p) + (n << 23));
}
__device__ __forceinline__ uint32_t pack_bf16x2(float lo, float hi) {
    uint32_t r;
    asm("cvt.rn.bf16x2.f32 %0, %1, %2;" : "=r"(r) : "f"(hi), "f"(lo));
    return r;
}
__device__ __forceinline__ void cp16(uint32_t dst, const void* src) {
    asm volatile("cp.async.cg.shared.global [%0], [%1], 16;\n"
                 :: "r"(dst), "l"(src));
}
#define CP_COMMIT() asm volatile("cp.async.commit_group;\n" ::: "memory")
#define CP_WAIT(n)  asm volatile("cp.async.wait_group %0;\n" :: "n"(n) : "memory")

#define LDSM_T_X4(r0, r1, r2, r3, addr)                                       \
    asm volatile("ldmatrix.sync.aligned.m8n8.x4.trans.shared.b16 "            \
                 "{%0,%1,%2,%3}, [%4];"                                       \
        : "=r"(r0), "=r"(r1), "=r"(r2), "=r"(r3) : "r"(addr))

// ---------------------------------------------------------------------------
// Batched weight transpose: Wo, W1, W2 -> fp16 [N][K] in ONE launch.
// tile = 32k x 64n.  Wo: 512 tiles, W1: 2048, W2: 2048.
// ---------------------------------------------------------------------------
__global__ void transpose_all_kernel(const float* __restrict__ Wo,
                                     const float* __restrict__ W1,
                                     const float* __restrict__ W2) {
    __shared__ float smw[32][68];
    int bid = blockIdx.x;
    const float* src; __half* dst; int K, N, bx, by;
    if (bid < 512) {
        src = Wo; dst = g_wor; K = CC; N = CC;
        bx = bid & 15; by = bid >> 4;            // 16 x 32
    } else if (bid < 2560) {
        int lb = bid - 512;
        src = W1; dst = g_w1r; K = CC; N = 4*CC;
        bx = lb & 63; by = lb >> 6;              // 64 x 32
    } else {
        int lb = bid - 2560;
        src = W2; dst = g_w2r; K = 4*CC; N = CC;
        bx = lb & 15; by = lb >> 4;              // 16 x 128
    }
    int n0 = bx * 64, k0 = by * 32;
    int tid = threadIdx.x;
    int r = tid >> 3, c8 = (tid & 7) * 8;
    *(float4*)&smw[r][c8]     = *(const float4*)&src[(size_t)(k0 + r)*N + n0 + c8];
    *(float4*)&smw[r][c8 + 4] = *(const float4*)&src[(size_t)(k0 + r)*N + n0 + c8 + 4];
    __syncthreads();
    int nl = tid >> 2, j = tid & 3;
    __half2 h0 = __floats2half2_rn(smw[j*8+0][nl], smw[j*8+1][nl]);
    __half2 h1 = __floats2half2_rn(smw[j*8+2][nl], smw[j*8+3][nl]);
    __half2 h2 = __floats2half2_rn(smw[j*8+4][nl], smw[j*8+5][nl]);
    __half2 h3 = __floats2half2_rn(smw[j*8+6][nl], smw[j*8+7][nl]);
    __half* d = dst + (size_t)(n0 + nl)*K + k0 + j*8;
    ((__half2*)d)[0] = h0; ((__half2*)d)[1] = h1;
    ((__half2*)d)[2] = h2; ((__half2*)d)[3] = h3;
}

// QKV weights -> Wt_qkv [n][k] fp16; Wq scaled by QSCALE.
__global__ void pack_qkv_wt_kernel(const float* __restrict__ Wq,
                                   const float* __restrict__ Wk,
                                   const float* __restrict__ Wv) {
    __shared__ float smw[32][68];
    int c0 = blockIdx.x * 32, h = blockIdx.y;
    int tid = threadIdx.x;
    int r = tid >> 3, c8 = (tid & 7) * 8;
    const float* srcs[3] = {Wq, Wk, Wv};
#pragma unroll
    for (int m = 0; m < 3; m++) {
        float sc = (m == 0) ? QSCALE : 1.0f;
        const float* s = srcs[m] + ((size_t)h*CC + c0)*HS;
        *(float4*)&smw[r][c8]     = *(const float4*)&s[(size_t)r*HS + c8];
        *(float4*)&smw[r][c8 + 4] = *(const float4*)&s[(size_t)r*HS + c8 + 4];
        __syncthreads();
        int nl = tid >> 2, j = tid & 3;
        __half2 h0 = __floats2half2_rn(smw[j*8+0][nl]*sc, smw[j*8+1][nl]*sc);
        __half2 h1 = __floats2half2_rn(smw[j*8+2][nl]*sc, smw[j*8+3][nl]*sc);
        __half2 h2 = __floats2half2_rn(smw[j*8+4][nl]*sc, smw[j*8+5][nl]*sc);
        __half2 h3 = __floats2half2_rn(smw[j*8+6][nl]*sc, smw[j*8+7][nl]*sc);
        __half* d = g_wqkv + (size_t)(m*CC + h*HS + nl)*CC + c0 + j*8;
        ((__half2*)d)[0] = h0; ((__half2*)d)[1] = h1;
        ((__half2*)d)[2] = h2; ((__half2*)d)[3] = h3;
        __syncthreads();
    }
}

__global__ void pack_bias_kernel(const float* __restrict__ bq,
                                 const float* __restrict__ bk,
                                 const float* __restrict__ bv) {
    int e = blockIdx.x * blockDim.x + threadIdx.x;
    if (e < CC) {
        g_bqkv[e]        = bq[e] * QSCALE;
        g_bqkv[CC + e]   = bk[e];
        g_bqkv[2*CC + e] = bv[e];
    }
}

// ---------------------------------------------------------------------------
// LayerNorm over sequence axis; fp16 output.
// ---------------------------------------------------------------------------
__global__ void __launch_bounds__(1024)
ln_seq_kernel(const float* __restrict__ x,
              const float* __restrict__ gamma,
              const float* __restrict__ beta,
              __half* __restrict__ out) {
    int b  = blockIdx.y;
    int tx = threadIdx.x, ty = threadIdx.y;
    int c  = blockIdx.x * 16 + tx;
    const float* xp = x   + (size_t)b*TT*CC + c;
    __half*      op = out + (size_t)b*TT*CC + c;

    float s = 0.f, sq = 0.f;
    for (int t = ty; t < TT; t += 64) {
        float v = xp[(size_t)t*CC];
        s += v; sq += v*v;
    }
    __shared__ float ssum[64][17];
    __shared__ float ssq [64][17];
    ssum[ty][tx] = s; ssq[ty][tx] = sq;
    __syncthreads();
    for (int off = 32; off > 0; off >>= 1) {
        if (ty < off) {
            ssum[ty][tx] += ssum[ty+off][tx];
            ssq [ty][tx] += ssq [ty+off][tx];
        }
        __syncthreads();
    }
    __shared__ float meanv[16], rstdv[16];
    if (ty == 0) {
        float mean = ssum[0][tx] * (1.0f / TT);
        float var  = (ssq[0][tx] - (float)TT * mean * mean) * (1.0f / (TT - 1));
        meanv[tx]  = mean;
        rstdv[tx]  = 1.0f / (sqrtf(var) + LN_EPS);
    }
    __syncthreads();
    float mean = meanv[tx], rstd = rstdv[tx];
    float g = gamma[c], bt = beta[c];
    for (int t = ty; t < TT; t += 64) {
        float v = xp[(size_t)t*CC];
        op[(size_t)t*CC] = __float2half(g * ((v - mean) * rstd) + bt);
    }
}

// ---------------------------------------------------------------------------
// fp16 GEMM m16n8k16, 128x128 tile, k-chunk 64, 2-stage cp.async (R15 verified)
// OUT: 0=f32, 1=f16, 2=bf16
// ---------------------------------------------------------------------------
#define MMA_F16(d, a, b)                                                      \
    asm volatile(                                                             \
        "mma.sync.aligned.m16n8k16.row.col.f32.f16.f16.f32 "                  \
        "{%0,%1,%2,%3},{%4,%5,%6,%7},{%8,%9},{%0,%1,%2,%3};\n"                \
        : "+f"((d)[0]), "+f"((d)[1]), "+f"((d)[2]), "+f"((d)[3])              \
        : "r"((a)[0]), "r"((a)[1]), "r"((a)[2]), "r"((a)[3]),                 \
          "r"((b)[0]), "r"((b)[1]))

#define AH_U32 36
#define ASZ (128*AH_U32)
#define GEMMH_SMEM (4*ASZ*4)

template<int DOBIAS, int DORELU, int DORES, int OUT>
__global__ void __launch_bounds__(256, 2)
gemm_h_kernel(const __half* __restrict__ A, const __half* __restrict__ Bt,
              const float* __restrict__ bias, const float* __restrict__ res,
              void* __restrict__ Cm, int M, int N, int K) {
    extern __shared__ uint32_t smg[];
    int tid  = threadIdx.x;
    int lane = tid & 31, wid = tid >> 5;
    int wm = (wid >> 1) * 32;
    int wn = (wid & 1) * 64;
    int g  = lane >> 2;
    int tg = lane & 3;
    int m0 = blockIdx.y * 128, n0 = blockIdx.x * 128;

    float acc[2][8][4];
#pragma unroll
    for (int mf = 0; mf < 2; mf++)
#pragma unroll
        for (int nf = 0; nf < 8; nf++)
#pragma unroll
            for (int r = 0; r < 4; r++) acc[mf][nf][r] = 0.f;

    uint32_t smg_u = (uint32_t)__cvta_generic_to_shared(smg);
    int nk = K >> 6;

#define STAGE_H(buf, k0)                                                      \
    do {                                                                      \
        uint32_t ab = smg_u + ((buf)*ASZ)*4;                                  \
        uint32_t bb = smg_u + ((2 + (buf))*ASZ)*4;                            \
        _Pragma("unroll")                                                     \
        for (int p = 0; p < 4; p++) {                                         \
            int idx = tid + p*256;                                            \
            int r = idx >> 3, c = idx & 7;                                    \
            cp16(ab + (r*AH_U32 + c*4)*4,                                     \
                 &A [(size_t)(m0 + r)*K + (k0) + c*8]);                       \
            cp16(bb + (r*AH_U32 + c*4)*4,                                     \
                 &Bt[(size_t)(n0 + r)*K + (k0) + c*8]);                       \
        }                                                                     \
        CP_COMMIT();                                                          \
    } while (0)

    STAGE_H(0, 0);

    for (int i = 0; i < nk; i++) {
        int buf = i & 1;
        if (i + 1 < nk) {
            STAGE_H((i + 1) & 1, (i + 1) << 6);
            CP_WAIT(1);
        } else {
            CP_WAIT(0);
        }
        __syncthreads();

        const uint32_t* As = smg + buf*ASZ;
        const uint32_t* Bs = smg + (2 + buf)*ASZ;

#pragma unroll
        for (int ks = 0; ks < 4; ks++) {
            int kk = ks * 8;
            uint32_t afr[2][4];
#pragma unroll
            for (int mf = 0; mf < 2; mf++) {
                int r = wm + mf*16 + g;
                afr[mf][0] = As[(r    )*AH_U32 + kk + tg    ];
                afr[mf][1] = As[(r + 8)*AH_U32 + kk + tg    ];
                afr[mf][2] = As[(r    )*AH_U32 + kk + tg + 4];
                afr[mf][3] = As[(r + 8)*AH_U32 + kk + tg + 4];
            }
#pragma unroll
            for (int nf = 0; nf < 8; nf++) {
                int n = wn + nf*8 + g;
                uint32_t bfr[2];
                bfr[0] = Bs[n*AH_U32 + kk + tg    ];
                bfr[1] = Bs[n*AH_U32 + kk + tg + 4];
#pragma unroll
                for (int mf = 0; mf < 2; mf++)
                    MMA_F16(acc[mf][nf], afr[mf], bfr);
            }
        }
        __syncthreads();
    }
#undef STAGE_H

#pragma unroll
    for (int mf = 0; mf < 2; mf++) {
#pragma unroll
        for (int nf = 0; nf < 8; nf++) {
            int r  = m0 + wm + mf*16 + g;
            int cb = n0 + wn + nf*8 + 2*tg;
            float2 v0 = make_float2(acc[mf][nf][0], acc[mf][nf][1]);
            float2 v1 = make_float2(acc[mf][nf][2], acc[mf][nf][3]);
            if (DOBIAS) {
                float2 bsv = *(const float2*)&bias[cb];
                v0.x += bsv.x; v0.y += bsv.y;
                v1.x += bsv.x; v1.y += bsv.y;
            }
            if (DORELU) {
                v0.x = fmaxf(v0.x, 0.f); v0.y = fmaxf(v0.y, 0.f);
                v1.x = fmaxf(v1.x, 0.f); v1.y = fmaxf(v1.y, 0.f);
            }
            if (DORES) {
                float2 r0 = *(const float2*)&res[(size_t)r*N + cb];
                float2 r1 = *(const float2*)&res[(size_t)(r+8)*N + cb];
                v0.x += r0.x; v0.y += r0.y;
                v1.x += r1.x; v1.y += r1.y;
            }
            if (OUT == 1) {
                __half* C = (__half*)Cm;
                *(__half2*)&C[(size_t)r*N + cb]     = __floats2half2_rn(v0.x, v0.y);
                *(__half2*)&C[(size_t)(r+8)*N + cb] = __floats2half2_rn(v1.x, v1.y);
            } else if (OUT == 2) {
                uint32_t* C = (uint32_t*)Cm;
                C[((size_t)r*N + cb) >> 1]     = pack_bf16x2(v0.x, v0.y);
                C[((size_t)(r+8)*N + cb) >> 1] = pack_bf16x2(v1.x, v1.y);
            } else {
                float* C = (float*)Cm;
                *(float2*)&C[(size_t)r*N + cb]     = v0;
                *(float2*)&C[(size_t)(r+8)*N + cb] = v1;
            }
        }
    }
}

// ---------------------------------------------------------------------------
// bf16 flash attention: cp.async double-buffered K/V (raw), V consumed via
// ldmatrix.trans.  Q pre-scaled.  smem: Qs[128][36] + 2xK[64][36] + 2xV[64][36]
// ---------------------------------------------------------------------------
#define QS32 36
#define KS32 36
#define VS32 36
#define SM32_QS 0
#define SM32_K0 (128*QS32)
#define SM32_V0 (SM32_K0 + 2*64*KS32)
#define ATTN_SMEM ((SM32_V0 + 2*64*VS32)*4)

#define MMA_BF16(d, a, b)                                                     \
    asm volatile(                                                             \
        "mma.sync.aligned.m16n8k16.row.col.f32.bf16.bf16.f32 "                \
        "{%0,%1,%2,%3},{%4,%5,%6,%7},{%8,%9},{%0,%1,%2,%3};\n"                \
        : "+f"((d)[0]), "+f"((d)[1]), "+f"((d)[2]), "+f"((d)[3])              \
        : "r"((a)[0]), "r"((a)[1]), "r"((a)[2]), "r"((a)[3]),                 \
          "r"((b)[0]), "r"((b)[1]))

__global__ void __launch_bounds__(256, 2) attn_tc_kernel() {
    extern __shared__ uint32_t smu[];
    uint32_t* Qs = smu + SM32_QS;
    uint32_t smb = (uint32_t)__cvta_generic_to_shared(smu);

    int tid = threadIdx.x, lane = tid & 31, wid = tid >> 5;
    int g = lane >> 2, tg = lane & 3;
    int b = blockIdx.z, h = blockIdx.y;
    int tq0 = blockIdx.x * 128;
    int wr = wid * 16;

    const __nv_bfloat16* qbase = g_qkv + (size_t)b*TT*3*CC + (size_t)h*HS;
    const __nv_bfloat16* kbase = qbase + CC;
    const __nv_bfloat16* vbase = qbase + 2*CC;

    // ldmatrix.trans lane addressing for V (row/col components)
    int vrow_l = ((lane >> 3) & 1)*8 + (lane & 7);   // + j*16
    int vcol_l = (lane >> 4) * 8;                     // + nfp*16, in halves

    // stage Q (raw copy, already scaled)
#pragma unroll
    for (int p = 0; p < 4; p++) {
        int idx = tid + p*256;
        int r = idx >> 3, c = idx & 7;
        uint4 v = *(const uint4*)&qbase[(size_t)(tq0 + r)*3*CC + c*8];
        *(uint4*)&Qs[r*QS32 + c*4] = v;
    }

    float o[8][4];
#pragma unroll
    for (int i = 0; i < 8; i++)
#pragma unroll
        for (int j = 0; j < 4; j++) o[i][j] = 0.f;
    float lsum0 = 0.f, lsum1 = 0.f;

    // K/V staging (raw rows of 64 halves = 8 x 16B), one commit group per tile
#define STAGE_KV(buf, kt)                                                     \
    do {                                                                      \
        uint32_t kb = smb + (SM32_K0 + (buf)*64*KS32)*4;                      \
        uint32_t vb = smb + (SM32_V0 + (buf)*64*VS32)*4;                      \
        _Pragma("unroll")                                                     \
        for (int p = 0; p < 2; p++) {                                         \
            int idx = tid + p*256;                                            \
            int r = idx >> 3, c = idx & 7;                                    \
            cp16(kb + (r*KS32 + c*4)*4,                                       \
                 &kbase[(size_t)((kt) + r)*3*CC + c*8]);                      \
            cp16(vb + (r*VS32 + c*4)*4,                                       \
                 &vbase[(size_t)((kt) + r)*3*CC + c*8]);                      \
        }                                                                     \
        CP_COMMIT();                                                          \
    } while (0)

    STAGE_KV(0, 0);
    __syncthreads();   // Q staged (plain stores) before first compute

    const int NT = TT / 64;
    for (int it = 0; it < NT; it++) {
        int buf = it & 1;
        if (it + 1 < NT) {
            STAGE_KV((it + 1) & 1, (it + 1) * 64);
            CP_WAIT(1);
        } else {
            CP_WAIT(0);
        }
        __syncthreads();

        const uint32_t* Ks = smu + SM32_K0 + buf*64*KS32;
        uint32_t vbufb = smb + (SM32_V0 + buf*64*VS32)*4;

        // ---- S = Q K^T
        float s[8][4];
#pragma unroll
        for (int nf = 0; nf < 8; nf++)
#pragma unroll
            for (int j = 0; j < 4; j++) s[nf][j] = 0.f;

#pragma unroll
        for (int c = 0; c < 4; c++) {
            int c8 = c * 8;
            uint32_t aq[4];
            aq[0] = Qs[(wr+g  )*QS32 + c8 + tg    ];
            aq[1] = Qs[(wr+g+8)*QS32 + c8 + tg    ];
            aq[2] = Qs[(wr+g  )*QS32 + c8 + tg + 4];
            aq[3] = Qs[(wr+g+8)*QS32 + c8 + tg + 4];
#pragma unroll
            for (int nf = 0; nf < 8; nf++) {
                uint32_t bk[2];
                bk[0] = Ks[(nf*8+g)*KS32 + c8 + tg    ];
                bk[1] = Ks[(nf*8+g)*KS32 + c8 + tg + 4];
                MMA_BF16(s[nf], aq, bk);
            }
        }

        // ---- exp2 (dual pipe) + row sums
#pragma unroll
        for (int nf = 0; nf < 8; nf++) {
            if (nf < 4) {
                s[nf][0] = ex2_mufu(fminf(s[nf][0], 80.f));
                s[nf][1] = ex2_mufu(fminf(s[nf][1], 80.f));
                s[nf][2] = ex2_mufu(fminf(s[nf][2], 80.f));
                s[nf][3] = ex2_mufu(fminf(s[nf][3], 80.f));
            } else {
                s[nf][0] = ex2_poly(fminf(fmaxf(s[nf][0], -80.f), 80.f));
                s[nf][1] = ex2_poly(fminf(fmaxf(s[nf][1], -80.f), 80.f));
                s[nf][2] = ex2_poly(fminf(fmaxf(s[nf][2], -80.f), 80.f));
                s[nf][3] = ex2_poly(fminf(fmaxf(s[nf][3], -80.f), 80.f));
            }
            lsum0 += s[nf][0] + s[nf][1];
            lsum1 += s[nf][2] + s[nf][3];
        }

        // ---- O += P V  (V B-frags via ldmatrix.trans from raw rows)
#pragma unroll
        for (int j = 0; j < 4; j++) {
            uint32_t ap[4];
            ap[0] = pack_bf16x2(s[2*j  ][0], s[2*j  ][1]);
            ap[1] = pack_bf16x2(s[2*j  ][2], s[2*j  ][3]);
            ap[2] = pack_bf16x2(s[2*j+1][0], s[2*j+1][1]);
            ap[3] = pack_bf16x2(s[2*j+1][2], s[2*j+1][3]);
            uint32_t rowb = vbufb + (uint32_t)(j*16 + vrow_l) * (VS32*4);
#pragma unroll
            for (int nfp = 0; nfp < 4; nfp++) {
                uint32_t b0, b1, b2, b3;
                LDSM_T_X4(b0, b1, b2, b3,
                          rowb + (uint32_t)(nfp*16 + vcol_l) * 2);
                uint32_t bv0[2] = {b0, b1};
                uint32_t bv1[2] = {b2, b3};
                MMA_BF16(o[2*nfp    ], ap, bv0);
                MMA_BF16(o[2*nfp + 1], ap, bv1);
            }
        }
        __syncthreads();
    }
#undef STAGE_KV

    lsum0 += __shfl_xor_sync(0xffffffffu, lsum0, 1);
    lsum0 += __shfl_xor_sync(0xffffffffu, lsum0, 2);
    lsum1 += __shfl_xor_sync(0xffffffffu, lsum1, 1);
    lsum1 += __shfl_xor_sync(0xffffffffu, lsum1, 2);
    float inv0 = 1.0f / lsum0, inv1 = 1.0f / lsum1;

    int row0 = b*TT + tq0 + wr + g;
#pragma unroll
    for (int nf = 0; nf < 8; nf++) {
        int col = h*HS + nf*8 + 2*tg;
        *(__half2*)&g_attn[(size_t)row0*CC + col] =
            __floats2half2_rn(o[nf][0]*inv0, o[nf][1]*inv0);
        *(__half2*)&g_attn[(size_t)(row0+8)*CC + col] =
            __floats2half2_rn(o[nf][2]*inv1, o[nf][3]*inv1);
    }
}

// ---------------------------------------------------------------------------
// Launch
// ---------------------------------------------------------------------------
extern "C" void kernel_launch(void* const* d_in, const int* in_sizes, int n_in,
                              void* d_out, int out_size) {
    const float* x      = (const float*)d_in[0];
    const float* Wq     = (const float*)d_in[1];
    const float* bq     = (const float*)d_in[2];
    const float* Wk     = (const float*)d_in[3];
    const float* bk     = (const float*)d_in[4];
    const float* Wv     = (const float*)d_in[5];
    const float* bv     = (const float*)d_in[6];
    const float* Wo     = (const float*)d_in[7];
    const float* bo     = (const float*)d_in[8];
    const float* W1     = (const float*)d_in[9];
    const float* b1     = (const float*)d_in[10];
    const float* W2     = (const float*)d_in[11];
    const float* b2     = (const float*)d_in[12];
    const float* gamma1 = (const float*)d_in[13];
    const float* beta1  = (const float*)d_in[14];
    const float* gamma2 = (const float*)d_in[15];
    const float* beta2  = (const float*)d_in[16];
    float* out = (float*)d_out;

    __half *p_h, *p_wqkv, *p_attn, *p_h2, *p_ff, *p_wor, *p_w1r, *p_w2r;
    float  *p_bqkv, *p_x1;
    __nv_bfloat16* p_qkv;
    cudaGetSymbolAddress((void**)&p_h,    g_h);
    cudaGetSymbolAddress((void**)&p_wqkv, g_wqkv);
    cudaGetSymbolAddress((void**)&p_bqkv, g_bqkv);
    cudaGetSymbolAddress((void**)&p_qkv,  g_qkv);
    cudaGetSymbolAddress((void**)&p_attn, g_attn);
    cudaGetSymbolAddress((void**)&p_x1,   g_x1);
    cudaGetSymbolAddress((void**)&p_h2,   g_h2);
    cudaGetSymbolAddress((void**)&p_ff,   g_ff);
    cudaGetSymbolAddress((void**)&p_wor,  g_wor);
    cudaGetSymbolAddress((void**)&p_w1r,  g_w1r);
    cudaGetSymbolAddress((void**)&p_w2r,  g_w2r);

    cudaFuncSetAttribute(attn_tc_kernel,
                         cudaFuncAttributeMaxDynamicSharedMemorySize, ATTN_SMEM);
    cudaFuncSetAttribute(gemm_h_kernel<1,0,0,2>,
                         cudaFuncAttributeMaxDynamicSharedMemorySize, GEMMH_SMEM);
    cudaFuncSetAttribute(gemm_h_kernel<1,0,1,0>,
                         cudaFuncAttributeMaxDynamicSharedMemorySize, GEMMH_SMEM);
    cudaFuncSetAttribute(gemm_h_kernel<1,1,0,1>,
                         cudaFuncAttributeMaxDynamicSharedMemorySize, GEMMH_SMEM);

    // 0. weight prep
    pack_qkv_wt_kernel<<<dim3(CC/32, HH), 256>>>(Wq, Wk, Wv);
    pack_bias_kernel<<<(CC + 255)/256, 256>>>(bq, bk, bv);
    transpose_all_kernel<<<4608, 256>>>(Wo, W1, W2);

    // 1. LN1 (fp16 out)
    ln_seq_kernel<<<dim3(CC/16, BB), dim3(16, 64)>>>(x, gamma1, beta1, p_h);

    // 2. QKV GEMM -> bf16 g_qkv (Q pre-scaled via weights)
    gemm_h_kernel<1,0,0,2><<<dim3(3*CC/128, NROWS/128), 256, GEMMH_SMEM>>>(
        p_h, p_wqkv, p_bqkv, nullptr, p_qkv, NROWS, 3*CC, CC);

    // 3. attention (bf16 in, fp16 out)
    attn_tc_kernel<<<dim3(TT/128, HH, BB), 256, ATTN_SMEM>>>();

    // 4. output projection + residual -> fp32 x1
    gemm_h_kernel<1,0,1,0><<<dim3(CC/128, NROWS/128), 256, GEMMH_SMEM>>>(
        p_attn, p_wor, bo, x, p_x1, NROWS, CC, CC);

    // 5. LN2 (fp16 out)
    ln_seq_kernel<<<dim3(CC/16, BB), dim3(16, 64)>>>(p_x1, gamma2, beta2, p_h2);

    // 6. FF1 + relu -> fp16 g_ff
    gemm_h_kernel<1,1,0,1><<<dim3(4*CC/128, NROWS/128), 256, GEMMH_SMEM>>>(
        p_h2, p_w1r, b1, nullptr, p_ff, NROWS, 4*CC, CC);

    // 7. FF2 + residual -> fp32 out
    gemm_h_kernel<1,0,1,0><<<dim3(CC/128, NROWS/128), 256, GEMMH_SMEM>>>(
        p_ff, p_w2r, b2, p_x1, out, NROWS, CC, 4*CC);
}